// round 14
// baseline (speedup 1.0000x reference)
#include <cuda_runtime.h>
#include <cuda_fp16.h>
#include <math.h>

#define N_SVC_ 100000
#define N_NODE_ 50000
#define FIN 16
#define HD0 128   // HEADS*HID
#define NH 4
#define OUTD 32
#define E_SS_ 800000
#define E_SN_ 400000
#define E_NS_ 400000
#define E_NN_ 400000
#define GBLK 592  // 4 blocks/SM on 148 SMs -> all resident, barrier is safe

// ---------------- static device scratch ----------------
__device__ int g_row_ss[N_SVC_ + 1], g_row_ns[N_SVC_ + 1];
__device__ int g_row_sn[N_NODE_ + 1], g_row_nn[N_NODE_ + 1];
__device__ int g_cur_ss[N_SVC_], g_cur_ns[N_SVC_];
__device__ int g_cur_sn[N_NODE_], g_cur_nn[N_NODE_];
__device__ int g_csr_ss[E_SS_], g_csr_sn[E_SN_], g_csr_ns[E_NS_], g_csr_nn[E_NN_];
__device__ unsigned g_arrive, g_release;   // monotonic across launches/replays

// layer-0 features (fp16 for gather bandwidth)
__device__ __align__(16) __half g_hs0s[2][N_SVC_ * HD0];   // r0(ss), r1(sn)
__device__ __align__(16) __half g_hs0n[2][N_NODE_ * HD0];  // r2(ns), r3(nn)
__device__ __align__(16) float g_as0s[2][N_SVC_ * NH];
__device__ __align__(16) float g_as0n[2][N_NODE_ * NH];
__device__ __align__(16) float g_ad0s[2][N_SVC_ * NH];
__device__ __align__(16) float g_ad0n[2][N_NODE_ * NH];
__device__ __align__(16) float g_hS[N_SVC_ * HD0];
__device__ __align__(16) float g_hN[N_NODE_ * HD0];
// layer-1 features (fp32)
__device__ __align__(16) float g_hs1s[2][N_SVC_ * OUTD];
__device__ __align__(16) float g_hs1n[2][N_NODE_ * OUTD];
__device__ float g_as1s[2][N_SVC_];
__device__ float g_as1n[2][N_NODE_];
__device__ float g_ad1s[2][N_SVC_];
__device__ float g_ad1n[2][N_NODE_];
__device__ __align__(16) float g_wdv0[4][FIN * NH];
__device__ __align__(16) float g_wdv1[4][HD0];
__device__ double g_pool[2 * OUTD];

struct RelDesc {
    const int* src; const int* dst;
    int E, Nd;
    int* row; int* cur; int* csr;
};
struct Rel4 { RelDesc r[4]; };

// ---------------- fused CSR build: one kernel, 4 phases, global barrier ----------------
__device__ __forceinline__ void gbar() {
    __syncthreads();
    __threadfence();
    if (threadIdx.x == 0) {
        unsigned my = atomicAdd(&g_arrive, 1u);
        unsigned gen = my / GBLK;
        if (my % GBLK == GBLK - 1u) atomicAdd(&g_release, 1u);
        while (atomicAdd(&g_release, 0u) <= gen) __nanosleep(64);
    }
    __syncthreads();
    __threadfence();
}

__global__ void __launch_bounds__(256, 4) k_csr(Rel4 R) {
    const int nthr = GBLK * 256;
    const int gtid = blockIdx.x * 256 + threadIdx.x;
    // P0: zero degree counters
#pragma unroll
    for (int r = 0; r < 4; r++) {
        const RelDesc rd = R.r[r];
        for (int i = gtid; i < rd.Nd; i += nthr) rd.cur[i] = 0;
    }
    gbar();
    // P1: histogram
#pragma unroll
    for (int r = 0; r < 4; r++) {
        const RelDesc rd = R.r[r];
        for (int e = gtid; e < rd.E; e += nthr) atomicAdd(&rd.cur[rd.dst[e]], 1);
    }
    gbar();
    // P2: exclusive scan, one block per relation (blocks 0-3)
    if (blockIdx.x < 4) {
        const RelDesc rd = R.r[blockIdx.x];
        int chunk = (rd.Nd + 255) / 256;
        int lo = threadIdx.x * chunk;
        int hi = lo + chunk; if (hi > rd.Nd) hi = rd.Nd;
        int s = 0;
        for (int i = lo; i < hi; i++) s += rd.cur[i];
        __shared__ int sh[256];
        sh[threadIdx.x] = s;
        __syncthreads();
        int v = s;
        for (int o = 1; o < 256; o <<= 1) {
            int a = (threadIdx.x >= o) ? sh[threadIdx.x - o] : 0;
            __syncthreads();
            sh[threadIdx.x] += a;
            __syncthreads();
        }
        if (threadIdx.x == 255) rd.row[rd.Nd] = sh[255];
        int run = sh[threadIdx.x] - v;
        for (int i = lo; i < hi; i++) {
            int c = rd.cur[i];
            rd.row[i] = run;
            rd.cur[i] = run;
            run += c;
        }
    }
    gbar();
    // P3: scatter src into CSR slots
#pragma unroll
    for (int r = 0; r < 4; r++) {
        const RelDesc rd = R.r[r];
        for (int e = gtid; e < rd.E; e += nthr) {
            int pos = atomicAdd(&rd.cur[rd.dst[e]], 1);
            rd.csr[pos] = rd.src[e];
        }
    }
}

// ---------------- wdv precompute + pool zero ----------------
__global__ void k_wdv_all(const float* __restrict__ Wd0, const float* __restrict__ ad0,
                          const float* __restrict__ Wd1, const float* __restrict__ ad1) {
    int t = threadIdx.x;  // 256
    {
        int r = t >> 6, f = (t >> 2) & 15, h = t & 3;
        float s = 0.f;
        for (int c = 0; c < 32; c++)
            s += Wd0[r * FIN * HD0 + f * HD0 + h * 32 + c] * ad0[r * HD0 + h * 32 + c];
        g_wdv0[r][f * NH + h] = s;
    }
    for (int i = t; i < 4 * HD0; i += 256) {
        int r = i >> 7, f = i & 127;
        float s = 0.f;
        for (int c = 0; c < OUTD; c++)
            s += Wd1[r * HD0 * OUTD + f * OUTD + c] * ad1[r * OUTD + c];
        g_wdv1[r][f] = s;
    }
    if (t < 2 * OUTD) g_pool[t] = 0.0;
}

// ---------------- layer-0 fused dense ----------------
struct Feat0Job {
    const float* x; int N;
    const float* Wa; const float* Wb; const float* atta; const float* attb;
    const float* wdvA; const float* wdvB;
    __half* hsa; __half* hsb;
    float* asra; float* asrb; float* adA; float* adB;
};
__global__ void k_feat0(Feat0Job j0, Feat0Job j1, int blocks0) {
    Feat0Job jb = (blockIdx.x < (unsigned)blocks0) ? j0 : j1;
    int bx = (blockIdx.x < (unsigned)blocks0) ? blockIdx.x : blockIdx.x - blocks0;
    __shared__ float sWa[FIN * HD0], sWb[FIN * HD0], sa[HD0], sb[HD0];
    __shared__ float swA[FIN * NH], swB[FIN * NH], sx[32 * FIN];
    int tid = threadIdx.x;  // 128
    for (int i = tid; i < FIN * HD0; i += 128) { sWa[i] = jb.Wa[i]; sWb[i] = jb.Wb[i]; }
    sa[tid] = jb.atta[tid]; sb[tid] = jb.attb[tid];
    if (tid < 64) { swA[tid] = jb.wdvA[tid]; swB[tid] = jb.wdvB[tid]; }
    int n0 = bx * 32;
    for (int i = tid; i < 32 * FIN; i += 128) {
        int nn = n0 + (i >> 4);
        sx[i] = (nn < jb.N) ? jb.x[nn * FIN + (i & 15)] : 0.f;
    }
    __syncthreads();
    int head = tid >> 5, lane = tid & 31;
    for (int jj = 0; jj < 32; jj++) {
        int n = n0 + jj;
        if (n >= jb.N) break;
        float va = 0.f, vb = 0.f;
#pragma unroll
        for (int f = 0; f < FIN; f++) {
            float xv = sx[jj * FIN + f];
            va += xv * sWa[f * HD0 + tid];
            vb += xv * sWb[f * HD0 + tid];
        }
        jb.hsa[(size_t)n * HD0 + tid] = __float2half_rn(va);
        jb.hsb[(size_t)n * HD0 + tid] = __float2half_rn(vb);
        float pa = va * sa[tid], pb = vb * sb[tid];
#pragma unroll
        for (int o = 16; o > 0; o >>= 1) {
            pa += __shfl_xor_sync(~0u, pa, o);
            pb += __shfl_xor_sync(~0u, pb, o);
        }
        if (lane == 0) { jb.asra[n * NH + head] = pa; jb.asrb[n * NH + head] = pb; }
    }
    for (int i = tid; i < 256; i += 128) {
        int jj = i >> 3, h = (i >> 1) & 3, r = i & 1;
        int n = n0 + jj;
        if (n < jb.N) {
            const float* w = r ? swB : swA;
            float s = 0.f;
#pragma unroll
            for (int f = 0; f < FIN; f++) s += sx[jj * FIN + f] * w[f * NH + h];
            (r ? jb.adB : jb.adA)[n * NH + h] = s;
        }
    }
}

// ---------------- layer-0 aggregation: warp/dst ----------------
struct Agg0Job {
    const int* rowA; const int* csrA; const float* asA; const float* adA;
    const __half* hsA; const float* bA;
    const int* rowB; const int* csrB; const float* asB; const float* adB;
    const __half* hsB; const float* bB;
    float* hout; int Nd;
};
__device__ __forceinline__ float4 agg0_rel(const int* __restrict__ row, const int* __restrict__ csr,
                                           const float* __restrict__ asr, const float* __restrict__ adt,
                                           const __half* __restrict__ hs, int d, int lane, int h) {
    float adv = adt[d * NH + h];
    int i0 = row[d], i1 = row[d + 1];
    float4 acc = make_float4(0.f, 0.f, 0.f, 0.f);
    float den = 0.f;
    const uint2* hrow = (const uint2*)hs;
    for (int i = i0; i < i1; i++) {
        int s = csr[i];
        float e = asr[s * NH + h] + adv;
        e = e > 0.f ? e : 0.2f * e;
        float w = __expf(e);
        den += w;
        uint2 raw = hrow[(size_t)s * 32 + lane];
        float2 f0 = __half22float2(*reinterpret_cast<const __half2*>(&raw.x));
        float2 f1 = __half22float2(*reinterpret_cast<const __half2*>(&raw.y));
        acc.x += w * f0.x; acc.y += w * f0.y; acc.z += w * f1.x; acc.w += w * f1.y;
    }
    float inv = 1.f / (den + 1e-16f);
    return make_float4(acc.x * inv, acc.y * inv, acc.z * inv, acc.w * inv);
}
__global__ void k_agg0(Agg0Job j0, Agg0Job j1, int blocks0) {
    Agg0Job jb = (blockIdx.x < (unsigned)blocks0) ? j0 : j1;
    int bx = (blockIdx.x < (unsigned)blocks0) ? blockIdx.x : blockIdx.x - blocks0;
    int d = bx * 8 + (threadIdx.x >> 5);
    if (d >= jb.Nd) return;
    int lane = threadIdx.x & 31, h = lane >> 3;
    float4 rA = agg0_rel(jb.rowA, jb.csrA, jb.asA, jb.adA, jb.hsA, d, lane, h);
    float4 rB = agg0_rel(jb.rowB, jb.csrB, jb.asB, jb.adB, jb.hsB, d, lane, h);
    float4 ba = ((const float4*)jb.bA)[lane], bb = ((const float4*)jb.bB)[lane];
    float4 o;
    o.x = 0.5f * (rA.x + rB.x + ba.x + bb.x);
    o.y = 0.5f * (rA.y + rB.y + ba.y + bb.y);
    o.z = 0.5f * (rA.z + rB.z + ba.z + bb.z);
    o.w = 0.5f * (rA.w + rB.w + ba.w + bb.w);
    o.x = o.x > 0.f ? o.x : expm1f(o.x);
    o.y = o.y > 0.f ? o.y : expm1f(o.y);
    o.z = o.z > 0.f ? o.z : expm1f(o.z);
    o.w = o.w > 0.f ? o.w : expm1f(o.w);
    ((float4*)jb.hout)[(size_t)d * 32 + lane] = o;
}

// ---------------- layer-1 fused dense ----------------
struct Feat1Job {
    const float* h; int N;
    const float* Wa; const float* Wb; const float* atta; const float* attb;
    const float* wdvA; const float* wdvB;
    float* h1a; float* h1b; float* asa; float* asb; float* adA; float* adB;
};
__global__ void k_feat1(Feat1Job j0, Feat1Job j1, int blocks0) {
    Feat1Job jb = (blockIdx.x < (unsigned)blocks0) ? j0 : j1;
    int bx = (blockIdx.x < (unsigned)blocks0) ? blockIdx.x : blockIdx.x - blocks0;
    __shared__ float sWa[HD0 * OUTD], sWb[HD0 * OUTD];
    __shared__ float sa[OUTD], sb[OUTD], swA[HD0], swB[HD0];
    int tid = threadIdx.x;  // 256
    for (int i = tid; i < HD0 * OUTD; i += 256) { sWa[i] = jb.Wa[i]; sWb[i] = jb.Wb[i]; }
    if (tid < OUTD) { sa[tid] = jb.atta[tid]; sb[tid] = jb.attb[tid]; }
    if (tid >= 64 && tid < 64 + HD0) { swA[tid - 64] = jb.wdvA[tid - 64]; swB[tid - 64] = jb.wdvB[tid - 64]; }
    __syncthreads();
    int warp = tid >> 5, lane = tid & 31;
    for (int t = 0; t < 4; t++) {
        int n = bx * 32 + warp * 4 + t;
        if (n >= jb.N) break;
        float4 hv = ((const float4*)jb.h)[(size_t)n * 32 + lane];
        float va = 0.f, vb = 0.f;
#pragma unroll
        for (int f = 0; f < HD0; f++) {
            float hf = __shfl_sync(~0u, ((const float*)&hv)[f & 3], f >> 2);
            va += hf * sWa[f * OUTD + lane];
            vb += hf * sWb[f * OUTD + lane];
        }
        jb.h1a[(size_t)n * OUTD + lane] = va;
        jb.h1b[(size_t)n * OUTD + lane] = vb;
        float pa = va * sa[lane], pb = vb * sb[lane];
        float4 wA = ((const float4*)swA)[lane], wB = ((const float4*)swB)[lane];
        float da = hv.x * wA.x + hv.y * wA.y + hv.z * wA.z + hv.w * wA.w;
        float db = hv.x * wB.x + hv.y * wB.y + hv.z * wB.z + hv.w * wB.w;
#pragma unroll
        for (int o = 16; o > 0; o >>= 1) {
            pa += __shfl_xor_sync(~0u, pa, o);
            pb += __shfl_xor_sync(~0u, pb, o);
            da += __shfl_xor_sync(~0u, da, o);
            db += __shfl_xor_sync(~0u, db, o);
        }
        if (lane == 0) { jb.asa[n] = pa; jb.asb[n] = pb; jb.adA[n] = da; jb.adB[n] = db; }
    }
}

// ---------------- layer-1 aggregation + fused mean-pool ----------------
struct Agg1Job {
    const int* rowA; const int* csrA; const float* asA; const float* adA;
    const float* h1A; const float* bA;
    const int* rowB; const int* csrB; const float* asB; const float* adB;
    const float* h1B; const float* bB;
    double* pool; int Nd;
};
__device__ __forceinline__ float agg1_rel(const int* __restrict__ row, const int* __restrict__ csr,
                                          const float* __restrict__ asr, const float* __restrict__ adt,
                                          const float* __restrict__ h1, int d, int lane) {
    float adv = adt[d];
    int i0 = row[d], i1 = row[d + 1];
    float acc = 0.f, den = 0.f;
    for (int i = i0; i < i1; i++) {
        int s = csr[i];
        float e = asr[s] + adv;
        e = e > 0.f ? e : 0.2f * e;
        float w = __expf(e);
        den += w;
        acc += w * h1[(size_t)s * OUTD + lane];
    }
    return acc / (den + 1e-16f);
}
__global__ void k_agg1(Agg1Job j0, Agg1Job j1, int blocks0) {
    Agg1Job jb = (blockIdx.x < (unsigned)blocks0) ? j0 : j1;
    int bx = (blockIdx.x < (unsigned)blocks0) ? blockIdx.x : blockIdx.x - blocks0;
    __shared__ double sp[8][33];
    int warp = threadIdx.x >> 5, lane = threadIdx.x & 31;
    int d = bx * 8 + warp;
    float res = 0.f;
    if (d < jb.Nd) {
        float rA = agg1_rel(jb.rowA, jb.csrA, jb.asA, jb.adA, jb.h1A, d, lane);
        float rB = agg1_rel(jb.rowB, jb.csrB, jb.asB, jb.adB, jb.h1B, d, lane);
        res = 0.5f * (rA + rB + jb.bA[lane] + jb.bB[lane]);
    }
    sp[warp][lane] = (double)res;
    __syncthreads();
    if (warp == 0) {
        double t = sp[0][lane];
#pragma unroll
        for (int k = 1; k < 8; k++) t += sp[k][lane];
        asm volatile("red.global.add.f64 [%0], %1;" :: "l"(&jb.pool[lane]), "d"(t) : "memory");
    }
}

__global__ void k_out(float* __restrict__ out) {
    int t = threadIdx.x;  // 64
    double cnt = (t < OUTD) ? (double)N_SVC_ : (double)N_NODE_;
    out[t] = (float)(g_pool[t] / cnt);
}

// ---------------- host driver (fork/join; CSR = single kernel on side stream) ----------------
extern "C" void kernel_launch(void* const* d_in, const int* in_sizes, int n_in,
                              void* d_out, int out_size) {
    const float* x_svc = (const float*)d_in[0];
    const float* x_node = (const float*)d_in[1];
    const int* ss_s = (const int*)d_in[2]; const int* ss_d = (const int*)d_in[3];
    const int* sn_s = (const int*)d_in[4]; const int* sn_d = (const int*)d_in[5];
    const int* ns_s = (const int*)d_in[6]; const int* ns_d = (const int*)d_in[7];
    const int* nn_s = (const int*)d_in[8]; const int* nn_d = (const int*)d_in[9];
    const float* Ws0 = (const float*)d_in[10];
    const float* Wd0 = (const float*)d_in[11];
    const float* as0 = (const float*)d_in[12];
    const float* ad0 = (const float*)d_in[13];
    const float* b0  = (const float*)d_in[14];
    const float* Ws1 = (const float*)d_in[15];
    const float* Wd1 = (const float*)d_in[16];
    const float* as1 = (const float*)d_in[17];
    const float* ad1 = (const float*)d_in[18];
    const float* b1  = (const float*)d_in[19];
    int E_ss = in_sizes[2], E_sn = in_sizes[4], E_ns = in_sizes[6], E_nn = in_sizes[8];

    int *row_ss, *row_sn, *row_ns, *row_nn, *cur_ss, *cur_sn, *cur_ns, *cur_nn;
    int *csr_ss, *csr_sn, *csr_ns, *csr_nn;
    __half *hs0s, *hs0n;
    float *as0s, *as0n, *ad0s, *ad0n, *hS, *hN;
    float *hs1s, *hs1n, *as1s, *as1n, *ad1s, *ad1n, *wdv0, *wdv1;
    double* pool;
    cudaGetSymbolAddress((void**)&row_ss, g_row_ss);
    cudaGetSymbolAddress((void**)&row_sn, g_row_sn);
    cudaGetSymbolAddress((void**)&row_ns, g_row_ns);
    cudaGetSymbolAddress((void**)&row_nn, g_row_nn);
    cudaGetSymbolAddress((void**)&cur_ss, g_cur_ss);
    cudaGetSymbolAddress((void**)&cur_sn, g_cur_sn);
    cudaGetSymbolAddress((void**)&cur_ns, g_cur_ns);
    cudaGetSymbolAddress((void**)&cur_nn, g_cur_nn);
    cudaGetSymbolAddress((void**)&csr_ss, g_csr_ss);
    cudaGetSymbolAddress((void**)&csr_sn, g_csr_sn);
    cudaGetSymbolAddress((void**)&csr_ns, g_csr_ns);
    cudaGetSymbolAddress((void**)&csr_nn, g_csr_nn);
    cudaGetSymbolAddress((void**)&hs0s, g_hs0s);
    cudaGetSymbolAddress((void**)&hs0n, g_hs0n);
    cudaGetSymbolAddress((void**)&as0s, g_as0s);
    cudaGetSymbolAddress((void**)&as0n, g_as0n);
    cudaGetSymbolAddress((void**)&ad0s, g_ad0s);
    cudaGetSymbolAddress((void**)&ad0n, g_ad0n);
    cudaGetSymbolAddress((void**)&hS, g_hS);
    cudaGetSymbolAddress((void**)&hN, g_hN);
    cudaGetSymbolAddress((void**)&hs1s, g_hs1s);
    cudaGetSymbolAddress((void**)&hs1n, g_hs1n);
    cudaGetSymbolAddress((void**)&as1s, g_as1s);
    cudaGetSymbolAddress((void**)&as1n, g_as1n);
    cudaGetSymbolAddress((void**)&ad1s, g_ad1s);
    cudaGetSymbolAddress((void**)&ad1n, g_ad1n);
    cudaGetSymbolAddress((void**)&wdv0, g_wdv0);
    cudaGetSymbolAddress((void**)&wdv1, g_wdv1);
    cudaGetSymbolAddress((void**)&pool, g_pool);

    Rel4 R;
    R.r[0] = {ss_s, ss_d, E_ss, N_SVC_,  row_ss, cur_ss, csr_ss};
    R.r[1] = {sn_s, sn_d, E_sn, N_NODE_, row_sn, cur_sn, csr_sn};
    R.r[2] = {ns_s, ns_d, E_ns, N_SVC_,  row_ns, cur_ns, csr_ns};
    R.r[3] = {nn_s, nn_d, E_nn, N_NODE_, row_nn, cur_nn, csr_nn};

    // fork: CSR build (one kernel) on side stream, dense chain on main stream
    cudaStream_t s2;
    cudaEvent_t evFork, evJoin;
    cudaStreamCreateWithFlags(&s2, cudaStreamNonBlocking);
    cudaEventCreateWithFlags(&evFork, cudaEventDisableTiming);
    cudaEventCreateWithFlags(&evJoin, cudaEventDisableTiming);

    cudaEventRecord(evFork, 0);
    cudaStreamWaitEvent(s2, evFork, 0);

    k_csr<<<GBLK, 256, 0, s2>>>(R);                 // submission index 0
    cudaEventRecord(evJoin, s2);

    // --- main stream: dense layer 0 ---
    k_wdv_all<<<1, 256>>>(Wd0, ad0, Wd1, ad1);      // index 1
    size_t SZS = (size_t)N_SVC_ * HD0, SZN = (size_t)N_NODE_ * HD0;
    {
        Feat0Job f0, f1;
        f0 = {x_svc, N_SVC_, Ws0 + 0 * FIN * HD0, Ws0 + 1 * FIN * HD0,
              as0 + 0 * HD0, as0 + 1 * HD0, wdv0 + 0 * 64, wdv0 + 2 * 64,
              hs0s, hs0s + SZS, as0s, as0s + N_SVC_ * NH, ad0s, ad0s + N_SVC_ * NH};
        f1 = {x_node, N_NODE_, Ws0 + 2 * FIN * HD0, Ws0 + 3 * FIN * HD0,
              as0 + 2 * HD0, as0 + 3 * HD0, wdv0 + 1 * 64, wdv0 + 3 * 64,
              hs0n, hs0n + SZN, as0n, as0n + N_NODE_ * NH, ad0n, ad0n + N_NODE_ * NH};
        int b0n = (N_SVC_ + 31) / 32;
        k_feat0<<<b0n + (N_NODE_ + 31) / 32, 128>>>(f0, f1, b0n);   // index 2
    }

    cudaStreamWaitEvent(0, evJoin, 0);
    {
        Agg0Job a0, a1;
        a0 = {row_ss, csr_ss, as0s, ad0s, hs0s, b0 + 0 * HD0,
              row_ns, csr_ns, as0n, ad0s + N_SVC_ * NH, hs0n, b0 + 2 * HD0,
              hS, N_SVC_};
        a1 = {row_sn, csr_sn, as0s + N_SVC_ * NH, ad0n, hs0s + SZS, b0 + 1 * HD0,
              row_nn, csr_nn, as0n + N_NODE_ * NH, ad0n + N_NODE_ * NH, hs0n + SZN, b0 + 3 * HD0,
              hN, N_NODE_};
        int b0n = (N_SVC_ + 7) / 8;
        k_agg0<<<b0n + (N_NODE_ + 7) / 8, 256>>>(a0, a1, b0n);      // index 3 -> profiled
    }

    // ---- layer 1 ----
    size_t S1S = (size_t)N_SVC_ * OUTD, S1N = (size_t)N_NODE_ * OUTD;
    {
        Feat1Job f0, f1;
        f0 = {hS, N_SVC_, Ws1 + 0 * HD0 * OUTD, Ws1 + 1 * HD0 * OUTD,
              as1 + 0 * OUTD, as1 + 1 * OUTD, wdv1 + 0 * HD0, wdv1 + 2 * HD0,
              hs1s, hs1s + S1S, as1s, as1s + N_SVC_, ad1s, ad1s + N_SVC_};
        f1 = {hN, N_NODE_, Ws1 + 2 * HD0 * OUTD, Ws1 + 3 * HD0 * OUTD,
              as1 + 2 * OUTD, as1 + 3 * OUTD, wdv1 + 1 * HD0, wdv1 + 3 * HD0,
              hs1n, hs1n + S1N, as1n, as1n + N_NODE_, ad1n, ad1n + N_NODE_};
        int b0n = (N_SVC_ + 31) / 32;
        k_feat1<<<b0n + (N_NODE_ + 31) / 32, 256>>>(f0, f1, b0n);
    }
    {
        Agg1Job a0, a1;
        a0 = {row_ss, csr_ss, as1s, ad1s, hs1s, b1 + 0 * OUTD,
              row_ns, csr_ns, as1n, ad1s + N_SVC_, hs1n, b1 + 2 * OUTD,
              pool, N_SVC_};
        a1 = {row_sn, csr_sn, as1s + N_SVC_, ad1n, hs1s + S1S, b1 + 1 * OUTD,
              row_nn, csr_nn, as1n + N_NODE_, ad1n + N_NODE_, hs1n + S1N, b1 + 3 * OUTD,
              pool + OUTD, N_NODE_};
        int b0n = (N_SVC_ + 7) / 8;
        k_agg1<<<b0n + (N_NODE_ + 7) / 8, 256>>>(a0, a1, b0n);
    }
    k_out<<<1, 64>>>((float*)d_out);
    // s2/evFork/evJoin intentionally not destroyed (illegal mid-capture; bounded leak)
}

// round 15
// speedup vs baseline: 1.5958x; 1.5958x over previous
#include <cuda_runtime.h>
#include <cuda_fp16.h>
#include <math.h>

#define N_SVC_ 100000
#define N_NODE_ 50000
#define FIN 16
#define HD0 128   // HEADS*HID
#define NH 4
#define OUTD 32
#define E_SS_ 800000
#define E_SN_ 400000
#define E_NS_ 400000
#define E_NN_ 400000

// ---------------- static device scratch ----------------
__device__ int g_row_ss[N_SVC_ + 1], g_row_ns[N_SVC_ + 1];
__device__ int g_row_sn[N_NODE_ + 1], g_row_nn[N_NODE_ + 1];
__device__ int g_cur_ss[N_SVC_], g_cur_ns[N_SVC_];
__device__ int g_cur_sn[N_NODE_], g_cur_nn[N_NODE_];
__device__ int g_csr_ss[E_SS_], g_csr_sn[E_SN_], g_csr_ns[E_NS_], g_csr_nn[E_NN_];
__device__ int g_bsumA[4][256];

// layer-0 features (fp16 for gather bandwidth)
__device__ __align__(16) __half g_hs0s[2][N_SVC_ * HD0];   // r0(ss), r1(sn)
__device__ __align__(16) __half g_hs0n[2][N_NODE_ * HD0];  // r2(ns), r3(nn)
__device__ __align__(16) float g_as0s[2][N_SVC_ * NH];
__device__ __align__(16) float g_as0n[2][N_NODE_ * NH];
__device__ __align__(16) float g_ad0s[2][N_SVC_ * NH];
__device__ __align__(16) float g_ad0n[2][N_NODE_ * NH];
__device__ __align__(16) float g_hS[N_SVC_ * HD0];
__device__ __align__(16) float g_hN[N_NODE_ * HD0];
// layer-1 features (fp32)
__device__ __align__(16) float g_hs1s[2][N_SVC_ * OUTD];
__device__ __align__(16) float g_hs1n[2][N_NODE_ * OUTD];
__device__ float g_as1s[2][N_SVC_];
__device__ float g_as1n[2][N_NODE_];
__device__ float g_ad1s[2][N_SVC_];
__device__ float g_ad1n[2][N_NODE_];
__device__ __align__(16) float g_wdv0[4][FIN * NH];
__device__ __align__(16) float g_wdv1[4][HD0];
__device__ double g_pool[2 * OUTD];

struct RelDesc {
    const int* src; const int* dst;
    int E, Nd;
    int* row; int* cur; int* csr; int* bsum;
};
struct Rel4 { RelDesc r[4]; };

// ---------------- wdv precompute + pool zero ----------------
__global__ void k_wdv_all(const float* __restrict__ Wd0, const float* __restrict__ ad0,
                          const float* __restrict__ Wd1, const float* __restrict__ ad1) {
    int t = threadIdx.x;  // 256
    {
        int r = t >> 6, f = (t >> 2) & 15, h = t & 3;
        float s = 0.f;
        for (int c = 0; c < 32; c++)
            s += Wd0[r * FIN * HD0 + f * HD0 + h * 32 + c] * ad0[r * HD0 + h * 32 + c];
        g_wdv0[r][f * NH + h] = s;
    }
    for (int i = t; i < 4 * HD0; i += 256) {
        int r = i >> 7, f = i & 127;
        float s = 0.f;
        for (int c = 0; c < OUTD; c++)
            s += Wd1[r * HD0 * OUTD + f * OUTD + c] * ad1[r * OUTD + c];
        g_wdv1[r][f] = s;
    }
    if (t < 2 * OUTD) g_pool[t] = 0.0;
}

// ---------------- CSR build ----------------
__global__ void k_zero_deg(Rel4 R) {
    const RelDesc rd = R.r[blockIdx.y];
    int i = blockIdx.x * 256 + threadIdx.x;
    if (i < rd.Nd) rd.cur[i] = 0;
}
__global__ void k_hist(Rel4 R) {
    const RelDesc rd = R.r[blockIdx.y];
    int e = blockIdx.x * 256 + threadIdx.x;
    if (e < rd.E) atomicAdd(&rd.cur[rd.dst[e]], 1);
}
__global__ void k_bsum(Rel4 R) {
    const RelDesc rd = R.r[blockIdx.y];
    if ((int)blockIdx.x * 512 >= rd.Nd) return;
    __shared__ int sh[512];
    int t = threadIdx.x, i = blockIdx.x * 512 + t;
    sh[t] = (i < rd.Nd) ? rd.cur[i] : 0;
    __syncthreads();
    for (int o = 256; o > 0; o >>= 1) {
        if (t < o) sh[t] += sh[t + o];
        __syncthreads();
    }
    if (t == 0) rd.bsum[blockIdx.x] = sh[0];
}
__global__ void k_bscan(Rel4 R) {
    const RelDesc rd = R.r[blockIdx.x];
    int nb = (rd.Nd + 511) >> 9;
    __shared__ int sh[256];
    int t = threadIdx.x;
    int v = (t < nb) ? rd.bsum[t] : 0;
    sh[t] = v;
    __syncthreads();
    for (int o = 1; o < 256; o <<= 1) {
        int a = (t >= o) ? sh[t - o] : 0;
        __syncthreads();
        sh[t] += a;
        __syncthreads();
    }
    if (t < nb) rd.bsum[t] = sh[t] - v;
    if (t == 255) rd.row[rd.Nd] = sh[255];
}
__global__ void k_rowptr(Rel4 R) {
    const RelDesc rd = R.r[blockIdx.y];
    if ((int)blockIdx.x * 512 >= rd.Nd) return;
    __shared__ int sh[512];
    int t = threadIdx.x, i = blockIdx.x * 512 + t;
    int v = (i < rd.Nd) ? rd.cur[i] : 0;
    sh[t] = v;
    __syncthreads();
    for (int o = 1; o < 512; o <<= 1) {
        int a = (t >= o) ? sh[t - o] : 0;
        __syncthreads();
        sh[t] += a;
        __syncthreads();
    }
    if (i < rd.Nd) {
        int rp = rd.bsum[blockIdx.x] + sh[t] - v;
        rd.row[i] = rp;
        rd.cur[i] = rp;
    }
}
__global__ void k_scatter(Rel4 R) {
    const RelDesc rd = R.r[blockIdx.y];
    int e = blockIdx.x * 256 + threadIdx.x;
    if (e < rd.E) {
        int pos = atomicAdd(&rd.cur[rd.dst[e]], 1);
        rd.csr[pos] = rd.src[e];
    }
}

// ---------------- layer-0 fused dense ----------------
struct Feat0Job {
    const float* x; int N;
    const float* Wa; const float* Wb; const float* atta; const float* attb;
    const float* wdvA; const float* wdvB;
    __half* hsa; __half* hsb;
    float* asra; float* asrb; float* adA; float* adB;
};
__global__ void k_feat0(Feat0Job j0, Feat0Job j1, int blocks0) {
    Feat0Job jb = (blockIdx.x < (unsigned)blocks0) ? j0 : j1;
    int bx = (blockIdx.x < (unsigned)blocks0) ? blockIdx.x : blockIdx.x - blocks0;
    __shared__ float sWa[FIN * HD0], sWb[FIN * HD0], sa[HD0], sb[HD0];
    __shared__ float swA[FIN * NH], swB[FIN * NH], sx[32 * FIN];
    int tid = threadIdx.x;  // 128
    for (int i = tid; i < FIN * HD0; i += 128) { sWa[i] = jb.Wa[i]; sWb[i] = jb.Wb[i]; }
    sa[tid] = jb.atta[tid]; sb[tid] = jb.attb[tid];
    if (tid < 64) { swA[tid] = jb.wdvA[tid]; swB[tid] = jb.wdvB[tid]; }
    int n0 = bx * 32;
    for (int i = tid; i < 32 * FIN; i += 128) {
        int nn = n0 + (i >> 4);
        sx[i] = (nn < jb.N) ? jb.x[nn * FIN + (i & 15)] : 0.f;
    }
    __syncthreads();
    int head = tid >> 5, lane = tid & 31;
    for (int jj = 0; jj < 32; jj++) {
        int n = n0 + jj;
        if (n >= jb.N) break;
        float va = 0.f, vb = 0.f;
#pragma unroll
        for (int f = 0; f < FIN; f++) {
            float xv = sx[jj * FIN + f];
            va += xv * sWa[f * HD0 + tid];
            vb += xv * sWb[f * HD0 + tid];
        }
        jb.hsa[(size_t)n * HD0 + tid] = __float2half_rn(va);
        jb.hsb[(size_t)n * HD0 + tid] = __float2half_rn(vb);
        float pa = va * sa[tid], pb = vb * sb[tid];
#pragma unroll
        for (int o = 16; o > 0; o >>= 1) {
            pa += __shfl_xor_sync(~0u, pa, o);
            pb += __shfl_xor_sync(~0u, pb, o);
        }
        if (lane == 0) { jb.asra[n * NH + head] = pa; jb.asrb[n * NH + head] = pb; }
    }
    for (int i = tid; i < 256; i += 128) {
        int jj = i >> 3, h = (i >> 1) & 3, r = i & 1;
        int n = n0 + jj;
        if (n < jb.N) {
            const float* w = r ? swB : swA;
            float s = 0.f;
#pragma unroll
            for (int f = 0; f < FIN; f++) s += sx[jj * FIN + f] * w[f * NH + h];
            (r ? jb.adB : jb.adA)[n * NH + h] = s;
        }
    }
}

// ---------------- layer-0 aggregation: warp/dst, 2x unrolled, fmax lrelu ----------------
struct Agg0Job {
    const int* rowA; const int* csrA; const float* asA; const float* adA;
    const __half* hsA; const float* bA;
    const int* rowB; const int* csrB; const float* asB; const float* adB;
    const __half* hsB; const float* bB;
    float* hout; int Nd;
};
__device__ __forceinline__ float ew_fast(float e) {
    e = fmaxf(e, 0.2f * e);           // leaky_relu(e, 0.2) for both signs
    return __expf(e);
}
__device__ __forceinline__ float4 agg0_rel(const int* __restrict__ row, const int* __restrict__ csr,
                                           const float* __restrict__ asr, const float* __restrict__ adt,
                                           const __half* __restrict__ hs, int d, int lane, int h) {
    float adv = adt[d * NH + h];
    int i0 = row[d], i1 = row[d + 1];
    float4 acc = make_float4(0.f, 0.f, 0.f, 0.f);
    float den = 0.f;
    const uint2* hrow = (const uint2*)hs;
    int i = i0;
    for (; i + 2 <= i1; i += 2) {
        int s0 = csr[i], s1 = csr[i + 1];
        float w0 = ew_fast(asr[s0 * NH + h] + adv);
        float w1 = ew_fast(asr[s1 * NH + h] + adv);
        uint2 r0 = hrow[(size_t)s0 * 32 + lane];
        uint2 r1 = hrow[(size_t)s1 * 32 + lane];
        den += w0 + w1;
        float2 a0 = __half22float2(*reinterpret_cast<const __half2*>(&r0.x));
        float2 a1 = __half22float2(*reinterpret_cast<const __half2*>(&r0.y));
        float2 b0 = __half22float2(*reinterpret_cast<const __half2*>(&r1.x));
        float2 b1 = __half22float2(*reinterpret_cast<const __half2*>(&r1.y));
        acc.x += w0 * a0.x + w1 * b0.x;
        acc.y += w0 * a0.y + w1 * b0.y;
        acc.z += w0 * a1.x + w1 * b1.x;
        acc.w += w0 * a1.y + w1 * b1.y;
    }
    if (i < i1) {
        int s = csr[i];
        float w = ew_fast(asr[s * NH + h] + adv);
        den += w;
        uint2 raw = hrow[(size_t)s * 32 + lane];
        float2 f0 = __half22float2(*reinterpret_cast<const __half2*>(&raw.x));
        float2 f1 = __half22float2(*reinterpret_cast<const __half2*>(&raw.y));
        acc.x += w * f0.x; acc.y += w * f0.y; acc.z += w * f1.x; acc.w += w * f1.y;
    }
    float inv = 1.f / (den + 1e-16f);
    return make_float4(acc.x * inv, acc.y * inv, acc.z * inv, acc.w * inv);
}
__global__ void k_agg0(Agg0Job j0, Agg0Job j1, int blocks0) {
    Agg0Job jb = (blockIdx.x < (unsigned)blocks0) ? j0 : j1;
    int bx = (blockIdx.x < (unsigned)blocks0) ? blockIdx.x : blockIdx.x - blocks0;
    int d = bx * 8 + (threadIdx.x >> 5);
    if (d >= jb.Nd) return;
    int lane = threadIdx.x & 31, h = lane >> 3;
    float4 rA = agg0_rel(jb.rowA, jb.csrA, jb.asA, jb.adA, jb.hsA, d, lane, h);
    float4 rB = agg0_rel(jb.rowB, jb.csrB, jb.asB, jb.adB, jb.hsB, d, lane, h);
    float4 ba = ((const float4*)jb.bA)[lane], bb = ((const float4*)jb.bB)[lane];
    float4 o;
    o.x = 0.5f * (rA.x + rB.x + ba.x + bb.x);
    o.y = 0.5f * (rA.y + rB.y + ba.y + bb.y);
    o.z = 0.5f * (rA.z + rB.z + ba.z + bb.z);
    o.w = 0.5f * (rA.w + rB.w + ba.w + bb.w);
    o.x = o.x > 0.f ? o.x : expm1f(o.x);
    o.y = o.y > 0.f ? o.y : expm1f(o.y);
    o.z = o.z > 0.f ? o.z : expm1f(o.z);
    o.w = o.w > 0.f ? o.w : expm1f(o.w);
    ((float4*)jb.hout)[(size_t)d * 32 + lane] = o;
}

// ---------------- layer-1 fused dense ----------------
struct Feat1Job {
    const float* h; int N;
    const float* Wa; const float* Wb; const float* atta; const float* attb;
    const float* wdvA; const float* wdvB;
    float* h1a; float* h1b; float* asa; float* asb; float* adA; float* adB;
};
__global__ void k_feat1(Feat1Job j0, Feat1Job j1, int blocks0) {
    Feat1Job jb = (blockIdx.x < (unsigned)blocks0) ? j0 : j1;
    int bx = (blockIdx.x < (unsigned)blocks0) ? blockIdx.x : blockIdx.x - blocks0;
    __shared__ float sWa[HD0 * OUTD], sWb[HD0 * OUTD];
    __shared__ float sa[OUTD], sb[OUTD], swA[HD0], swB[HD0];
    int tid = threadIdx.x;  // 256
    for (int i = tid; i < HD0 * OUTD; i += 256) { sWa[i] = jb.Wa[i]; sWb[i] = jb.Wb[i]; }
    if (tid < OUTD) { sa[tid] = jb.atta[tid]; sb[tid] = jb.attb[tid]; }
    if (tid >= 64 && tid < 64 + HD0) { swA[tid - 64] = jb.wdvA[tid - 64]; swB[tid - 64] = jb.wdvB[tid - 64]; }
    __syncthreads();
    int warp = tid >> 5, lane = tid & 31;
    for (int t = 0; t < 4; t++) {
        int n = bx * 32 + warp * 4 + t;
        if (n >= jb.N) break;
        float4 hv = ((const float4*)jb.h)[(size_t)n * 32 + lane];
        float va = 0.f, vb = 0.f;
#pragma unroll
        for (int f = 0; f < HD0; f++) {
            float hf = __shfl_sync(~0u, ((const float*)&hv)[f & 3], f >> 2);
            va += hf * sWa[f * OUTD + lane];
            vb += hf * sWb[f * OUTD + lane];
        }
        jb.h1a[(size_t)n * OUTD + lane] = va;
        jb.h1b[(size_t)n * OUTD + lane] = vb;
        float pa = va * sa[lane], pb = vb * sb[lane];
        float4 wA = ((const float4*)swA)[lane], wB = ((const float4*)swB)[lane];
        float da = hv.x * wA.x + hv.y * wA.y + hv.z * wA.z + hv.w * wA.w;
        float db = hv.x * wB.x + hv.y * wB.y + hv.z * wB.z + hv.w * wB.w;
#pragma unroll
        for (int o = 16; o > 0; o >>= 1) {
            pa += __shfl_xor_sync(~0u, pa, o);
            pb += __shfl_xor_sync(~0u, pb, o);
            da += __shfl_xor_sync(~0u, da, o);
            db += __shfl_xor_sync(~0u, db, o);
        }
        if (lane == 0) { jb.asa[n] = pa; jb.asb[n] = pb; jb.adA[n] = da; jb.adB[n] = db; }
    }
}

// ---------------- layer-1 aggregation: 2x unrolled + fused mean-pool ----------------
struct Agg1Job {
    const int* rowA; const int* csrA; const float* asA; const float* adA;
    const float* h1A; const float* bA;
    const int* rowB; const int* csrB; const float* asB; const float* adB;
    const float* h1B; const float* bB;
    double* pool; int Nd;
};
__device__ __forceinline__ float agg1_rel(const int* __restrict__ row, const int* __restrict__ csr,
                                          const float* __restrict__ asr, const float* __restrict__ adt,
                                          const float* __restrict__ h1, int d, int lane) {
    float adv = adt[d];
    int i0 = row[d], i1 = row[d + 1];
    float acc = 0.f, den = 0.f;
    int i = i0;
    for (; i + 2 <= i1; i += 2) {
        int s0 = csr[i], s1 = csr[i + 1];
        float w0 = ew_fast(asr[s0] + adv);
        float w1 = ew_fast(asr[s1] + adv);
        float v0 = h1[(size_t)s0 * OUTD + lane];
        float v1 = h1[(size_t)s1 * OUTD + lane];
        den += w0 + w1;
        acc += w0 * v0 + w1 * v1;
    }
    if (i < i1) {
        int s = csr[i];
        float w = ew_fast(asr[s] + adv);
        den += w;
        acc += w * h1[(size_t)s * OUTD + lane];
    }
    return acc / (den + 1e-16f);
}
__global__ void k_agg1(Agg1Job j0, Agg1Job j1, int blocks0) {
    Agg1Job jb = (blockIdx.x < (unsigned)blocks0) ? j0 : j1;
    int bx = (blockIdx.x < (unsigned)blocks0) ? blockIdx.x : blockIdx.x - blocks0;
    __shared__ double sp[8][33];
    int warp = threadIdx.x >> 5, lane = threadIdx.x & 31;
    int d = bx * 8 + warp;
    float res = 0.f;
    if (d < jb.Nd) {
        float rA = agg1_rel(jb.rowA, jb.csrA, jb.asA, jb.adA, jb.h1A, d, lane);
        float rB = agg1_rel(jb.rowB, jb.csrB, jb.asB, jb.adB, jb.h1B, d, lane);
        res = 0.5f * (rA + rB + jb.bA[lane] + jb.bB[lane]);
    }
    sp[warp][lane] = (double)res;
    __syncthreads();
    if (warp == 0) {
        double t = sp[0][lane];
#pragma unroll
        for (int k = 1; k < 8; k++) t += sp[k][lane];
        asm volatile("red.global.add.f64 [%0], %1;" :: "l"(&jb.pool[lane]), "d"(t) : "memory");
    }
}

__global__ void k_out(float* __restrict__ out) {
    int t = threadIdx.x;  // 64
    double cnt = (t < OUTD) ? (double)N_SVC_ : (double)N_NODE_;
    out[t] = (float)(g_pool[t] / cnt);
}

// ---------------- host driver (R13 fork/join: CSR build overlaps wdv+feat0) ----------------
extern "C" void kernel_launch(void* const* d_in, const int* in_sizes, int n_in,
                              void* d_out, int out_size) {
    const float* x_svc = (const float*)d_in[0];
    const float* x_node = (const float*)d_in[1];
    const int* ss_s = (const int*)d_in[2]; const int* ss_d = (const int*)d_in[3];
    const int* sn_s = (const int*)d_in[4]; const int* sn_d = (const int*)d_in[5];
    const int* ns_s = (const int*)d_in[6]; const int* ns_d = (const int*)d_in[7];
    const int* nn_s = (const int*)d_in[8]; const int* nn_d = (const int*)d_in[9];
    const float* Ws0 = (const float*)d_in[10];
    const float* Wd0 = (const float*)d_in[11];
    const float* as0 = (const float*)d_in[12];
    const float* ad0 = (const float*)d_in[13];
    const float* b0  = (const float*)d_in[14];
    const float* Ws1 = (const float*)d_in[15];
    const float* Wd1 = (const float*)d_in[16];
    const float* as1 = (const float*)d_in[17];
    const float* ad1 = (const float*)d_in[18];
    const float* b1  = (const float*)d_in[19];
    int E_ss = in_sizes[2], E_sn = in_sizes[4], E_ns = in_sizes[6], E_nn = in_sizes[8];

    int *row_ss, *row_sn, *row_ns, *row_nn, *cur_ss, *cur_sn, *cur_ns, *cur_nn;
    int *csr_ss, *csr_sn, *csr_ns, *csr_nn, *bsumA;
    __half *hs0s, *hs0n;
    float *as0s, *as0n, *ad0s, *ad0n, *hS, *hN;
    float *hs1s, *hs1n, *as1s, *as1n, *ad1s, *ad1n, *wdv0, *wdv1;
    double* pool;
    cudaGetSymbolAddress((void**)&row_ss, g_row_ss);
    cudaGetSymbolAddress((void**)&row_sn, g_row_sn);
    cudaGetSymbolAddress((void**)&row_ns, g_row_ns);
    cudaGetSymbolAddress((void**)&row_nn, g_row_nn);
    cudaGetSymbolAddress((void**)&cur_ss, g_cur_ss);
    cudaGetSymbolAddress((void**)&cur_sn, g_cur_sn);
    cudaGetSymbolAddress((void**)&cur_ns, g_cur_ns);
    cudaGetSymbolAddress((void**)&cur_nn, g_cur_nn);
    cudaGetSymbolAddress((void**)&csr_ss, g_csr_ss);
    cudaGetSymbolAddress((void**)&csr_sn, g_csr_sn);
    cudaGetSymbolAddress((void**)&csr_ns, g_csr_ns);
    cudaGetSymbolAddress((void**)&csr_nn, g_csr_nn);
    cudaGetSymbolAddress((void**)&bsumA, g_bsumA);
    cudaGetSymbolAddress((void**)&hs0s, g_hs0s);
    cudaGetSymbolAddress((void**)&hs0n, g_hs0n);
    cudaGetSymbolAddress((void**)&as0s, g_as0s);
    cudaGetSymbolAddress((void**)&as0n, g_as0n);
    cudaGetSymbolAddress((void**)&ad0s, g_ad0s);
    cudaGetSymbolAddress((void**)&ad0n, g_ad0n);
    cudaGetSymbolAddress((void**)&hS, g_hS);
    cudaGetSymbolAddress((void**)&hN, g_hN);
    cudaGetSymbolAddress((void**)&hs1s, g_hs1s);
    cudaGetSymbolAddress((void**)&hs1n, g_hs1n);
    cudaGetSymbolAddress((void**)&as1s, g_as1s);
    cudaGetSymbolAddress((void**)&as1n, g_as1n);
    cudaGetSymbolAddress((void**)&ad1s, g_ad1s);
    cudaGetSymbolAddress((void**)&ad1n, g_ad1n);
    cudaGetSymbolAddress((void**)&wdv0, g_wdv0);
    cudaGetSymbolAddress((void**)&wdv1, g_wdv1);
    cudaGetSymbolAddress((void**)&pool, g_pool);

    Rel4 R;
    R.r[0] = {ss_s, ss_d, E_ss, N_SVC_,  row_ss, cur_ss, csr_ss, bsumA + 0 * 256};
    R.r[1] = {sn_s, sn_d, E_sn, N_NODE_, row_sn, cur_sn, csr_sn, bsumA + 1 * 256};
    R.r[2] = {ns_s, ns_d, E_ns, N_SVC_,  row_ns, cur_ns, csr_ns, bsumA + 2 * 256};
    R.r[3] = {nn_s, nn_d, E_nn, N_NODE_, row_nn, cur_nn, csr_nn, bsumA + 3 * 256};

    int maxE = E_ss > E_sn ? E_ss : E_sn;
    if (E_ns > maxE) maxE = E_ns;
    if (E_nn > maxE) maxE = E_nn;

    // fork: CSR build on side stream, dense chain on main (legacy) stream
    cudaStream_t s2;
    cudaEvent_t evFork, evJoin;
    cudaStreamCreateWithFlags(&s2, cudaStreamNonBlocking);
    cudaEventCreateWithFlags(&evFork, cudaEventDisableTiming);
    cudaEventCreateWithFlags(&evJoin, cudaEventDisableTiming);

    cudaEventRecord(evFork, 0);
    cudaStreamWaitEvent(s2, evFork, 0);

    // --- side stream: CSR build ---
    k_zero_deg<<<dim3((N_SVC_ + 255) / 256, 4), 256, 0, s2>>>(R);
    k_hist<<<dim3((maxE + 255) / 256, 4), 256, 0, s2>>>(R);
    k_bsum<<<dim3((N_SVC_ + 511) / 512, 4), 512, 0, s2>>>(R);
    k_bscan<<<4, 256, 0, s2>>>(R);
    k_rowptr<<<dim3((N_SVC_ + 511) / 512, 4), 512, 0, s2>>>(R);
    k_scatter<<<dim3((maxE + 255) / 256, 4), 256, 0, s2>>>(R);
    cudaEventRecord(evJoin, s2);

    // --- main stream: dense layer 0 ---
    k_wdv_all<<<1, 256>>>(Wd0, ad0, Wd1, ad1);
    size_t SZS = (size_t)N_SVC_ * HD0, SZN = (size_t)N_NODE_ * HD0;
    {
        Feat0Job f0, f1;
        f0 = {x_svc, N_SVC_, Ws0 + 0 * FIN * HD0, Ws0 + 1 * FIN * HD0,
              as0 + 0 * HD0, as0 + 1 * HD0, wdv0 + 0 * 64, wdv0 + 2 * 64,
              hs0s, hs0s + SZS, as0s, as0s + N_SVC_ * NH, ad0s, ad0s + N_SVC_ * NH};
        f1 = {x_node, N_NODE_, Ws0 + 2 * FIN * HD0, Ws0 + 3 * FIN * HD0,
              as0 + 2 * HD0, as0 + 3 * HD0, wdv0 + 1 * 64, wdv0 + 3 * 64,
              hs0n, hs0n + SZN, as0n, as0n + N_NODE_ * NH, ad0n, ad0n + N_NODE_ * NH};
        int b0n = (N_SVC_ + 31) / 32;
        k_feat0<<<b0n + (N_NODE_ + 31) / 32, 128>>>(f0, f1, b0n);
    }

    // join: agg0 needs both CSR and feat0
    cudaStreamWaitEvent(0, evJoin, 0);
    {
        Agg0Job a0, a1;
        a0 = {row_ss, csr_ss, as0s, ad0s, hs0s, b0 + 0 * HD0,
              row_ns, csr_ns, as0n, ad0s + N_SVC_ * NH, hs0n, b0 + 2 * HD0,
              hS, N_SVC_};
        a1 = {row_sn, csr_sn, as0s + N_SVC_ * NH, ad0n, hs0s + SZS, b0 + 1 * HD0,
              row_nn, csr_nn, as0n + N_NODE_ * NH, ad0n + N_NODE_ * NH, hs0n + SZN, b0 + 3 * HD0,
              hN, N_NODE_};
        int b0n = (N_SVC_ + 7) / 8;
        k_agg0<<<b0n + (N_NODE_ + 7) / 8, 256>>>(a0, a1, b0n);
    }

    // ---- layer 1 ----
    size_t S1S = (size_t)N_SVC_ * OUTD, S1N = (size_t)N_NODE_ * OUTD;
    {
        Feat1Job f0, f1;
        f0 = {hS, N_SVC_, Ws1 + 0 * HD0 * OUTD, Ws1 + 1 * HD0 * OUTD,
              as1 + 0 * OUTD, as1 + 1 * OUTD, wdv1 + 0 * HD0, wdv1 + 2 * HD0,
              hs1s, hs1s + S1S, as1s, as1s + N_SVC_, ad1s, ad1s + N_SVC_};
        f1 = {hN, N_NODE_, Ws1 + 2 * HD0 * OUTD, Ws1 + 3 * HD0 * OUTD,
              as1 + 2 * OUTD, as1 + 3 * OUTD, wdv1 + 1 * HD0, wdv1 + 3 * HD0,
              hs1n, hs1n + S1N, as1n, as1n + N_NODE_, ad1n, ad1n + N_NODE_};
        int b0n = (N_SVC_ + 31) / 32;
        k_feat1<<<b0n + (N_NODE_ + 31) / 32, 256>>>(f0, f1, b0n);
    }
    {
        Agg1Job a0, a1;
        a0 = {row_ss, csr_ss, as1s, ad1s, hs1s, b1 + 0 * OUTD,
              row_ns, csr_ns, as1n, ad1s + N_SVC_, hs1n, b1 + 2 * OUTD,
              pool, N_SVC_};
        a1 = {row_sn, csr_sn, as1s + N_SVC_, ad1n, hs1s + S1S, b1 + 1 * OUTD,
              row_nn, csr_nn, as1n + N_NODE_, ad1n + N_NODE_, hs1n + S1N, b1 + 3 * OUTD,
              pool + OUTD, N_NODE_};
        int b0n = (N_SVC_ + 7) / 8;
        k_agg1<<<b0n + (N_NODE_ + 7) / 8, 256>>>(a0, a1, b0n);
    }
    k_out<<<1, 64>>>((float*)d_out);
    // s2/evFork/evJoin intentionally not destroyed (illegal mid-capture; bounded leak)
}

// round 16
// speedup vs baseline: 1.8031x; 1.1299x over previous
#include <cuda_runtime.h>
#include <cuda_fp16.h>
#include <math.h>

#define N_SVC_ 100000
#define N_NODE_ 50000
#define FIN 16
#define HD0 128   // HEADS*HID
#define NH 4
#define OUTD 32
#define E_SS_ 800000
#define E_SN_ 400000
#define E_NS_ 400000
#define E_NN_ 400000

// ---------------- static device scratch ----------------
__device__ int g_row_ss[N_SVC_ + 1], g_row_ns[N_SVC_ + 1];
__device__ int g_row_sn[N_NODE_ + 1], g_row_nn[N_NODE_ + 1];
__device__ int g_cur_ss[N_SVC_], g_cur_ns[N_SVC_];
__device__ int g_cur_sn[N_NODE_], g_cur_nn[N_NODE_];
__device__ int g_csr_ss[E_SS_], g_csr_sn[E_SN_], g_csr_ns[E_NS_], g_csr_nn[E_NN_];
__device__ int g_bsumA[4][256];

// layer-0: logits + aggregated-x (64 floats per dst per relation)
__device__ __align__(16) float g_as0s[2][N_SVC_ * NH];   // [0]=ss, [1]=sn (src=svc)
__device__ __align__(16) float g_as0n[2][N_NODE_ * NH];  // [0]=ns, [1]=nn (src=node)
__device__ __align__(16) float g_ad0s[2][N_SVC_ * NH];   // [0]=ss, [1]=ns (dst=svc)
__device__ __align__(16) float g_ad0n[2][N_NODE_ * NH];  // [0]=sn, [1]=nn (dst=node)
__device__ __align__(16) float g_aggx_ss[N_SVC_ * 64];
__device__ __align__(16) float g_aggx_ns[N_SVC_ * 64];
__device__ __align__(16) float g_aggx_sn[N_NODE_ * 64];
__device__ __align__(16) float g_aggx_nn[N_NODE_ * 64];
__device__ __align__(16) float g_hS[N_SVC_ * HD0];
__device__ __align__(16) float g_hN[N_NODE_ * HD0];
// layer-1 features (fp32)
__device__ __align__(16) float g_hs1s[2][N_SVC_ * OUTD];
__device__ __align__(16) float g_hs1n[2][N_NODE_ * OUTD];
__device__ float g_as1s[2][N_SVC_];
__device__ float g_as1n[2][N_NODE_];
__device__ float g_ad1s[2][N_SVC_];
__device__ float g_ad1n[2][N_NODE_];
__device__ __align__(16) float g_wdv0[4][FIN * NH];
__device__ __align__(16) float g_wsv0[4][FIN * NH];
__device__ __align__(16) float g_wdv1[4][HD0];
__device__ double g_pool[2 * OUTD];

struct RelDesc {
    const int* src; const int* dst;
    int E, Nd;
    int* row; int* cur; int* csr; int* bsum;
};
struct Rel4 { RelDesc r[4]; };

// ---------------- wdv/wsv precompute + pool zero ----------------
__global__ void k_wdv_all(const float* __restrict__ Ws0, const float* __restrict__ as0,
                          const float* __restrict__ Wd0, const float* __restrict__ ad0,
                          const float* __restrict__ Wd1, const float* __restrict__ ad1) {
    int t = threadIdx.x;  // 256
    {
        int r = t >> 6, f = (t >> 2) & 15, h = t & 3;
        float s1 = 0.f, s2 = 0.f;
        for (int c = 0; c < 32; c++) {
            s1 += Wd0[r * FIN * HD0 + f * HD0 + h * 32 + c] * ad0[r * HD0 + h * 32 + c];
            s2 += Ws0[r * FIN * HD0 + f * HD0 + h * 32 + c] * as0[r * HD0 + h * 32 + c];
        }
        g_wdv0[r][f * NH + h] = s1;
        g_wsv0[r][f * NH + h] = s2;
    }
    for (int i = t; i < 4 * HD0; i += 256) {
        int r = i >> 7, f = i & 127;
        float s = 0.f;
        for (int c = 0; c < OUTD; c++)
            s += Wd1[r * HD0 * OUTD + f * OUTD + c] * ad1[r * OUTD + c];
        g_wdv1[r][f] = s;
    }
    if (t < 2 * OUTD) g_pool[t] = 0.0;
}

// ---------------- CSR build (unchanged) ----------------
__global__ void k_zero_deg(Rel4 R) {
    const RelDesc rd = R.r[blockIdx.y];
    int i = blockIdx.x * 256 + threadIdx.x;
    if (i < rd.Nd) rd.cur[i] = 0;
}
__global__ void k_hist(Rel4 R) {
    const RelDesc rd = R.r[blockIdx.y];
    int e = blockIdx.x * 256 + threadIdx.x;
    if (e < rd.E) atomicAdd(&rd.cur[rd.dst[e]], 1);
}
__global__ void k_bsum(Rel4 R) {
    const RelDesc rd = R.r[blockIdx.y];
    if ((int)blockIdx.x * 512 >= rd.Nd) return;
    __shared__ int sh[512];
    int t = threadIdx.x, i = blockIdx.x * 512 + t;
    sh[t] = (i < rd.Nd) ? rd.cur[i] : 0;
    __syncthreads();
    for (int o = 256; o > 0; o >>= 1) {
        if (t < o) sh[t] += sh[t + o];
        __syncthreads();
    }
    if (t == 0) rd.bsum[blockIdx.x] = sh[0];
}
__global__ void k_bscan(Rel4 R) {
    const RelDesc rd = R.r[blockIdx.x];
    int nb = (rd.Nd + 511) >> 9;
    __shared__ int sh[256];
    int t = threadIdx.x;
    int v = (t < nb) ? rd.bsum[t] : 0;
    sh[t] = v;
    __syncthreads();
    for (int o = 1; o < 256; o <<= 1) {
        int a = (t >= o) ? sh[t - o] : 0;
        __syncthreads();
        sh[t] += a;
        __syncthreads();
    }
    if (t < nb) rd.bsum[t] = sh[t] - v;
    if (t == 255) rd.row[rd.Nd] = sh[255];
}
__global__ void k_rowptr(Rel4 R) {
    const RelDesc rd = R.r[blockIdx.y];
    if ((int)blockIdx.x * 512 >= rd.Nd) return;
    __shared__ int sh[512];
    int t = threadIdx.x, i = blockIdx.x * 512 + t;
    int v = (i < rd.Nd) ? rd.cur[i] : 0;
    sh[t] = v;
    __syncthreads();
    for (int o = 1; o < 512; o <<= 1) {
        int a = (t >= o) ? sh[t - o] : 0;
        __syncthreads();
        sh[t] += a;
        __syncthreads();
    }
    if (i < rd.Nd) {
        int rp = rd.bsum[blockIdx.x] + sh[t] - v;
        rd.row[i] = rp;
        rd.cur[i] = rp;
    }
}
__global__ void k_scatter(Rel4 R) {
    const RelDesc rd = R.r[blockIdx.y];
    int e = blockIdx.x * 256 + threadIdx.x;
    if (e < rd.E) {
        int pos = atomicAdd(&rd.cur[rd.dst[e]], 1);
        rd.csr[pos] = rd.src[e];
    }
}

// ---------------- layer-0 logits: asrc/adst for both relations of each type ----------------
struct Logit0Job {
    const float* x; int N;
    const float* wsvA; const float* wsvB; const float* wdvA; const float* wdvB;
    float* asA; float* asB; float* adA; float* adB;
};
__global__ void k_logit0(Logit0Job j0, Logit0Job j1, int blocks0) {
    Logit0Job jb = (blockIdx.x < (unsigned)blocks0) ? j0 : j1;
    int bx = (blockIdx.x < (unsigned)blocks0) ? blockIdx.x : blockIdx.x - blocks0;
    int n = bx * 256 + threadIdx.x;
    if (n >= jb.N) return;
    float xv[16];
    float4 t0 = ((const float4*)jb.x)[n * 4 + 0];
    float4 t1 = ((const float4*)jb.x)[n * 4 + 1];
    float4 t2 = ((const float4*)jb.x)[n * 4 + 2];
    float4 t3 = ((const float4*)jb.x)[n * 4 + 3];
    xv[0]=t0.x; xv[1]=t0.y; xv[2]=t0.z; xv[3]=t0.w;
    xv[4]=t1.x; xv[5]=t1.y; xv[6]=t1.z; xv[7]=t1.w;
    xv[8]=t2.x; xv[9]=t2.y; xv[10]=t2.z; xv[11]=t2.w;
    xv[12]=t3.x; xv[13]=t3.y; xv[14]=t3.z; xv[15]=t3.w;
#define DOT4(W, OUT) { \
        float d0=0,d1=0,d2=0,d3=0; \
        _Pragma("unroll") \
        for (int f = 0; f < 16; f++) { \
            float v = xv[f]; \
            d0 += v * (W)[f*4+0]; d1 += v * (W)[f*4+1]; \
            d2 += v * (W)[f*4+2]; d3 += v * (W)[f*4+3]; \
        } \
        ((float4*)(OUT))[n] = make_float4(d0,d1,d2,d3); }
    DOT4(jb.wsvA, jb.asA)
    DOT4(jb.wsvB, jb.asB)
    DOT4(jb.wdvA, jb.adA)
    DOT4(jb.wdvB, jb.adB)
#undef DOT4
}

// ---------------- layer-0 aggregation over raw x (linear-commute), warp/dst ----------------
struct Agg0Job {
    const int* rowA; const int* csrA; const float* asA; const float* adA; const float* xA;
    const int* rowB; const int* csrB; const float* asB; const float* adB; const float* xB;
    float* aggxA; float* aggxB; int Nd;
};
__device__ __forceinline__ float ew_fast(float e) {
    e = fmaxf(e, 0.2f * e);           // leaky_relu(e, 0.2)
    return __expf(e);
}
__device__ __forceinline__ float2 agg0x_rel(const int* __restrict__ row, const int* __restrict__ csr,
                                            const float* __restrict__ asr, const float* __restrict__ adt,
                                            const float* __restrict__ x, int d, int q, int h) {
    float adv = adt[d * NH + h];
    int i0 = row[d], i1 = row[d + 1];
    float ax = 0.f, ay = 0.f, den = 0.f;
    const float2* x2 = (const float2*)x;
    int i = i0;
    for (; i + 2 <= i1; i += 2) {
        int s0 = csr[i], s1 = csr[i + 1];
        float w0 = ew_fast(asr[s0 * NH + h] + adv);
        float w1 = ew_fast(asr[s1 * NH + h] + adv);
        float2 v0 = x2[s0 * 8 + q];
        float2 v1 = x2[s1 * 8 + q];
        den += w0 + w1;
        ax += w0 * v0.x + w1 * v1.x;
        ay += w0 * v0.y + w1 * v1.y;
    }
    if (i < i1) {
        int s = csr[i];
        float w = ew_fast(asr[s * NH + h] + adv);
        float2 v = x2[s * 8 + q];
        den += w;
        ax += w * v.x;
        ay += w * v.y;
    }
    float inv = 1.f / (den + 1e-16f);
    return make_float2(ax * inv, ay * inv);
}
__global__ void k_agg0(Agg0Job j0, Agg0Job j1, int blocks0) {
    Agg0Job jb = (blockIdx.x < (unsigned)blocks0) ? j0 : j1;
    int bx = (blockIdx.x < (unsigned)blocks0) ? blockIdx.x : blockIdx.x - blocks0;
    int d = bx * 8 + (threadIdx.x >> 5);
    if (d >= jb.Nd) return;
    int lane = threadIdx.x & 31, h = lane >> 3, q = lane & 7;
    float2 rA = agg0x_rel(jb.rowA, jb.csrA, jb.asA, jb.adA, jb.xA, d, q, h);
    float2 rB = agg0x_rel(jb.rowB, jb.csrB, jb.asB, jb.adB, jb.xB, d, q, h);
    ((float2*)jb.aggxA)[(size_t)d * 32 + lane] = rA;   // [h*16 + q*2] floats
    ((float2*)jb.aggxB)[(size_t)d * 32 + lane] = rB;
}

// ---------------- layer-0 post: out = 0.5*(aggxA@WsA + aggxB@WsB + bA + bB), ELU ----------------
struct Post0Job {
    const float* aggxA; const float* aggxB;
    const float* WsA; const float* WsB;
    const float* bA; const float* bB;
    float* hout; int N;
};
__global__ void k_post0(Post0Job j0, Post0Job j1, int blocks0) {
    Post0Job jb = (blockIdx.x < (unsigned)blocks0) ? j0 : j1;
    int bx = (blockIdx.x < (unsigned)blocks0) ? blockIdx.x : blockIdx.x - blocks0;
    __shared__ float sWa[FIN * HD0], sWb[FIN * HD0];
    __shared__ float sxa[32 * 64], sxb[32 * 64];
    int t = threadIdx.x;  // 128
    for (int i = t; i < FIN * HD0; i += 128) { sWa[i] = jb.WsA[i]; sWb[i] = jb.WsB[i]; }
    int n0 = bx * 32;
    int lim = jb.N - n0; if (lim > 32) lim = 32;
    for (int i = t; i < lim * 64; i += 128) {
        sxa[i] = jb.aggxA[(size_t)n0 * 64 + i];
        sxb[i] = jb.aggxB[(size_t)n0 * 64 + i];
    }
    __syncthreads();
    int h = t >> 5;
    float ba = jb.bA[t], bb = jb.bB[t];
    for (int jj = 0; jj < lim; jj++) {
        const float* axA = sxa + jj * 64 + h * 16;
        const float* axB = sxb + jj * 64 + h * 16;
        float sA = 0.f, sB = 0.f;
#pragma unroll
        for (int f = 0; f < 16; f++) {
            sA += axA[f] * sWa[f * HD0 + t];
            sB += axB[f] * sWb[f * HD0 + t];
        }
        float o = 0.5f * (sA + sB + ba + bb);
        jb.hout[(size_t)(n0 + jj) * HD0 + t] = o > 0.f ? o : expm1f(o);
    }
}

// ---------------- layer-1 fused dense (R15 body, unchanged) ----------------
struct Feat1Job {
    const float* h; int N;
    const float* Wa; const float* Wb; const float* atta; const float* attb;
    const float* wdvA; const float* wdvB;
    float* h1a; float* h1b; float* asa; float* asb; float* adA; float* adB;
};
__global__ void k_feat1(Feat1Job j0, Feat1Job j1, int blocks0) {
    Feat1Job jb = (blockIdx.x < (unsigned)blocks0) ? j0 : j1;
    int bx = (blockIdx.x < (unsigned)blocks0) ? blockIdx.x : blockIdx.x - blocks0;
    __shared__ float sWa[HD0 * OUTD], sWb[HD0 * OUTD];
    __shared__ float sa[OUTD], sb[OUTD], swA[HD0], swB[HD0];
    int tid = threadIdx.x;  // 256
    for (int i = tid; i < HD0 * OUTD; i += 256) { sWa[i] = jb.Wa[i]; sWb[i] = jb.Wb[i]; }
    if (tid < OUTD) { sa[tid] = jb.atta[tid]; sb[tid] = jb.attb[tid]; }
    if (tid >= 64 && tid < 64 + HD0) { swA[tid - 64] = jb.wdvA[tid - 64]; swB[tid - 64] = jb.wdvB[tid - 64]; }
    __syncthreads();
    int warp = tid >> 5, lane = tid & 31;
    for (int t = 0; t < 4; t++) {
        int n = bx * 32 + warp * 4 + t;
        if (n >= jb.N) break;
        float4 hv = ((const float4*)jb.h)[(size_t)n * 32 + lane];
        float va = 0.f, vb = 0.f;
#pragma unroll
        for (int f = 0; f < HD0; f++) {
            float hf = __shfl_sync(~0u, ((const float*)&hv)[f & 3], f >> 2);
            va += hf * sWa[f * OUTD + lane];
            vb += hf * sWb[f * OUTD + lane];
        }
        jb.h1a[(size_t)n * OUTD + lane] = va;
        jb.h1b[(size_t)n * OUTD + lane] = vb;
        float pa = va * sa[lane], pb = vb * sb[lane];
        float4 wA = ((const float4*)swA)[lane], wB = ((const float4*)swB)[lane];
        float da = hv.x * wA.x + hv.y * wA.y + hv.z * wA.z + hv.w * wA.w;
        float db = hv.x * wB.x + hv.y * wB.y + hv.z * wB.z + hv.w * wB.w;
#pragma unroll
        for (int o = 16; o > 0; o >>= 1) {
            pa += __shfl_xor_sync(~0u, pa, o);
            pb += __shfl_xor_sync(~0u, pb, o);
            da += __shfl_xor_sync(~0u, da, o);
            db += __shfl_xor_sync(~0u, db, o);
        }
        if (lane == 0) { jb.asa[n] = pa; jb.asb[n] = pb; jb.adA[n] = da; jb.adB[n] = db; }
    }
}

// ---------------- layer-1 aggregation (R15 body) + fused mean-pool ----------------
struct Agg1Job {
    const int* rowA; const int* csrA; const float* asA; const float* adA;
    const float* h1A; const float* bA;
    const int* rowB; const int* csrB; const float* asB; const float* adB;
    const float* h1B; const float* bB;
    double* pool; int Nd;
};
__device__ __forceinline__ float agg1_rel(const int* __restrict__ row, const int* __restrict__ csr,
                                          const float* __restrict__ asr, const float* __restrict__ adt,
                                          const float* __restrict__ h1, int d, int lane) {
    float adv = adt[d];
    int i0 = row[d], i1 = row[d + 1];
    float acc = 0.f, den = 0.f;
    int i = i0;
    for (; i + 2 <= i1; i += 2) {
        int s0 = csr[i], s1 = csr[i + 1];
        float w0 = ew_fast(asr[s0] + adv);
        float w1 = ew_fast(asr[s1] + adv);
        float v0 = h1[(size_t)s0 * OUTD + lane];
        float v1 = h1[(size_t)s1 * OUTD + lane];
        den += w0 + w1;
        acc += w0 * v0 + w1 * v1;
    }
    if (i < i1) {
        int s = csr[i];
        float w = ew_fast(asr[s] + adv);
        den += w;
        acc += w * h1[(size_t)s * OUTD + lane];
    }
    return acc / (den + 1e-16f);
}
__global__ void k_agg1(Agg1Job j0, Agg1Job j1, int blocks0) {
    Agg1Job jb = (blockIdx.x < (unsigned)blocks0) ? j0 : j1;
    int bx = (blockIdx.x < (unsigned)blocks0) ? blockIdx.x : blockIdx.x - blocks0;
    __shared__ double sp[8][33];
    int warp = threadIdx.x >> 5, lane = threadIdx.x & 31;
    int d = bx * 8 + warp;
    float res = 0.f;
    if (d < jb.Nd) {
        float rA = agg1_rel(jb.rowA, jb.csrA, jb.asA, jb.adA, jb.h1A, d, lane);
        float rB = agg1_rel(jb.rowB, jb.csrB, jb.asB, jb.adB, jb.h1B, d, lane);
        res = 0.5f * (rA + rB + jb.bA[lane] + jb.bB[lane]);
    }
    sp[warp][lane] = (double)res;
    __syncthreads();
    if (warp == 0) {
        double t = sp[0][lane];
#pragma unroll
        for (int k = 1; k < 8; k++) t += sp[k][lane];
        asm volatile("red.global.add.f64 [%0], %1;" :: "l"(&jb.pool[lane]), "d"(t) : "memory");
    }
}

__global__ void k_out(float* __restrict__ out) {
    int t = threadIdx.x;  // 64
    double cnt = (t < OUTD) ? (double)N_SVC_ : (double)N_NODE_;
    out[t] = (float)(g_pool[t] / cnt);
}

// ---------------- host driver (R13/R15 fork/join) ----------------
extern "C" void kernel_launch(void* const* d_in, const int* in_sizes, int n_in,
                              void* d_out, int out_size) {
    const float* x_svc = (const float*)d_in[0];
    const float* x_node = (const float*)d_in[1];
    const int* ss_s = (const int*)d_in[2]; const int* ss_d = (const int*)d_in[3];
    const int* sn_s = (const int*)d_in[4]; const int* sn_d = (const int*)d_in[5];
    const int* ns_s = (const int*)d_in[6]; const int* ns_d = (const int*)d_in[7];
    const int* nn_s = (const int*)d_in[8]; const int* nn_d = (const int*)d_in[9];
    const float* Ws0 = (const float*)d_in[10];
    const float* Wd0 = (const float*)d_in[11];
    const float* as0 = (const float*)d_in[12];
    const float* ad0 = (const float*)d_in[13];
    const float* b0  = (const float*)d_in[14];
    const float* Ws1 = (const float*)d_in[15];
    const float* Wd1 = (const float*)d_in[16];
    const float* as1 = (const float*)d_in[17];
    const float* ad1 = (const float*)d_in[18];
    const float* b1  = (const float*)d_in[19];
    int E_ss = in_sizes[2], E_sn = in_sizes[4], E_ns = in_sizes[6], E_nn = in_sizes[8];

    int *row_ss, *row_sn, *row_ns, *row_nn, *cur_ss, *cur_sn, *cur_ns, *cur_nn;
    int *csr_ss, *csr_sn, *csr_ns, *csr_nn, *bsumA;
    float *as0s, *as0n, *ad0s, *ad0n, *hS, *hN;
    float *aggx_ss, *aggx_ns, *aggx_sn, *aggx_nn;
    float *hs1s, *hs1n, *as1s, *as1n, *ad1s, *ad1n, *wdv0, *wsv0, *wdv1;
    double* pool;
    cudaGetSymbolAddress((void**)&row_ss, g_row_ss);
    cudaGetSymbolAddress((void**)&row_sn, g_row_sn);
    cudaGetSymbolAddress((void**)&row_ns, g_row_ns);
    cudaGetSymbolAddress((void**)&row_nn, g_row_nn);
    cudaGetSymbolAddress((void**)&cur_ss, g_cur_ss);
    cudaGetSymbolAddress((void**)&cur_sn, g_cur_sn);
    cudaGetSymbolAddress((void**)&cur_ns, g_cur_ns);
    cudaGetSymbolAddress((void**)&cur_nn, g_cur_nn);
    cudaGetSymbolAddress((void**)&csr_ss, g_csr_ss);
    cudaGetSymbolAddress((void**)&csr_sn, g_csr_sn);
    cudaGetSymbolAddress((void**)&csr_ns, g_csr_ns);
    cudaGetSymbolAddress((void**)&csr_nn, g_csr_nn);
    cudaGetSymbolAddress((void**)&bsumA, g_bsumA);
    cudaGetSymbolAddress((void**)&as0s, g_as0s);
    cudaGetSymbolAddress((void**)&as0n, g_as0n);
    cudaGetSymbolAddress((void**)&ad0s, g_ad0s);
    cudaGetSymbolAddress((void**)&ad0n, g_ad0n);
    cudaGetSymbolAddress((void**)&aggx_ss, g_aggx_ss);
    cudaGetSymbolAddress((void**)&aggx_ns, g_aggx_ns);
    cudaGetSymbolAddress((void**)&aggx_sn, g_aggx_sn);
    cudaGetSymbolAddress((void**)&aggx_nn, g_aggx_nn);
    cudaGetSymbolAddress((void**)&hS, g_hS);
    cudaGetSymbolAddress((void**)&hN, g_hN);
    cudaGetSymbolAddress((void**)&hs1s, g_hs1s);
    cudaGetSymbolAddress((void**)&hs1n, g_hs1n);
    cudaGetSymbolAddress((void**)&as1s, g_as1s);
    cudaGetSymbolAddress((void**)&as1n, g_as1n);
    cudaGetSymbolAddress((void**)&ad1s, g_ad1s);
    cudaGetSymbolAddress((void**)&ad1n, g_ad1n);
    cudaGetSymbolAddress((void**)&wdv0, g_wdv0);
    cudaGetSymbolAddress((void**)&wsv0, g_wsv0);
    cudaGetSymbolAddress((void**)&wdv1, g_wdv1);
    cudaGetSymbolAddress((void**)&pool, g_pool);

    Rel4 R;
    R.r[0] = {ss_s, ss_d, E_ss, N_SVC_,  row_ss, cur_ss, csr_ss, bsumA + 0 * 256};
    R.r[1] = {sn_s, sn_d, E_sn, N_NODE_, row_sn, cur_sn, csr_sn, bsumA + 1 * 256};
    R.r[2] = {ns_s, ns_d, E_ns, N_SVC_,  row_ns, cur_ns, csr_ns, bsumA + 2 * 256};
    R.r[3] = {nn_s, nn_d, E_nn, N_NODE_, row_nn, cur_nn, csr_nn, bsumA + 3 * 256};

    int maxE = E_ss > E_sn ? E_ss : E_sn;
    if (E_ns > maxE) maxE = E_ns;
    if (E_nn > maxE) maxE = E_nn;

    // fork: CSR build on side stream, dense chain on main (legacy) stream
    cudaStream_t s2;
    cudaEvent_t evFork, evJoin;
    cudaStreamCreateWithFlags(&s2, cudaStreamNonBlocking);
    cudaEventCreateWithFlags(&evFork, cudaEventDisableTiming);
    cudaEventCreateWithFlags(&evJoin, cudaEventDisableTiming);

    cudaEventRecord(evFork, 0);
    cudaStreamWaitEvent(s2, evFork, 0);

    // --- side stream: CSR build ---
    k_zero_deg<<<dim3((N_SVC_ + 255) / 256, 4), 256, 0, s2>>>(R);
    k_hist<<<dim3((maxE + 255) / 256, 4), 256, 0, s2>>>(R);
    k_bsum<<<dim3((N_SVC_ + 511) / 512, 4), 512, 0, s2>>>(R);
    k_bscan<<<4, 256, 0, s2>>>(R);
    k_rowptr<<<dim3((N_SVC_ + 511) / 512, 4), 512, 0, s2>>>(R);
    k_scatter<<<dim3((maxE + 255) / 256, 4), 256, 0, s2>>>(R);
    cudaEventRecord(evJoin, s2);

    // --- main stream: layer-0 logits ---
    k_wdv_all<<<1, 256>>>(Ws0, as0, Wd0, ad0, Wd1, ad1);
    {
        Logit0Job f0, f1;
        f0 = {x_svc, N_SVC_, wsv0 + 0 * 64, wsv0 + 1 * 64, wdv0 + 0 * 64, wdv0 + 2 * 64,
              as0s, as0s + N_SVC_ * NH, ad0s, ad0s + N_SVC_ * NH};
        f1 = {x_node, N_NODE_, wsv0 + 2 * 64, wsv0 + 3 * 64, wdv0 + 1 * 64, wdv0 + 3 * 64,
              as0n, as0n + N_NODE_ * NH, ad0n, ad0n + N_NODE_ * NH};
        int b0n = (N_SVC_ + 255) / 256;
        k_logit0<<<b0n + (N_NODE_ + 255) / 256, 256>>>(f0, f1, b0n);
    }

    // join: agg0 needs CSR + logits
    cudaStreamWaitEvent(0, evJoin, 0);
    {
        Agg0Job a0, a1;
        a0 = {row_ss, csr_ss, as0s, ad0s, x_svc,
              row_ns, csr_ns, as0n, ad0s + N_SVC_ * NH, x_node,
              aggx_ss, aggx_ns, N_SVC_};
        a1 = {row_sn, csr_sn, as0s + N_SVC_ * NH, ad0n, x_svc,
              row_nn, csr_nn, as0n + N_NODE_ * NH, ad0n + N_NODE_ * NH, x_node,
              aggx_sn, aggx_nn, N_NODE_};
        int b0n = (N_SVC_ + 7) / 8;
        k_agg0<<<b0n + (N_NODE_ + 7) / 8, 256>>>(a0, a1, b0n);
    }
    {
        Post0Job p0, p1;
        p0 = {aggx_ss, aggx_ns, Ws0 + 0 * FIN * HD0, Ws0 + 2 * FIN * HD0,
              b0 + 0 * HD0, b0 + 2 * HD0, hS, N_SVC_};
        p1 = {aggx_sn, aggx_nn, Ws0 + 1 * FIN * HD0, Ws0 + 3 * FIN * HD0,
              b0 + 1 * HD0, b0 + 3 * HD0, hN, N_NODE_};
        int b0n = (N_SVC_ + 31) / 32;
        k_post0<<<b0n + (N_NODE_ + 31) / 32, 128>>>(p0, p1, b0n);
    }

    // ---- layer 1 (unchanged) ----
    size_t S1S = (size_t)N_SVC_ * OUTD, S1N = (size_t)N_NODE_ * OUTD;
    {
        Feat1Job f0, f1;
        f0 = {hS, N_SVC_, Ws1 + 0 * HD0 * OUTD, Ws1 + 1 * HD0 * OUTD,
              as1 + 0 * OUTD, as1 + 1 * OUTD, wdv1 + 0 * HD0, wdv1 + 2 * HD0,
              hs1s, hs1s + S1S, as1s, as1s + N_SVC_, ad1s, ad1s + N_SVC_};
        f1 = {hN, N_NODE_, Ws1 + 2 * HD0 * OUTD, Ws1 + 3 * HD0 * OUTD,
              as1 + 2 * OUTD, as1 + 3 * OUTD, wdv1 + 1 * HD0, wdv1 + 3 * HD0,
              hs1n, hs1n + S1N, as1n, as1n + N_NODE_, ad1n, ad1n + N_NODE_};
        int b0n = (N_SVC_ + 31) / 32;
        k_feat1<<<b0n + (N_NODE_ + 31) / 32, 256>>>(f0, f1, b0n);
    }
    {
        Agg1Job a0, a1;
        a0 = {row_ss, csr_ss, as1s, ad1s, hs1s, b1 + 0 * OUTD,
              row_ns, csr_ns, as1n, ad1s + N_SVC_, hs1n, b1 + 2 * OUTD,
              pool, N_SVC_};
        a1 = {row_sn, csr_sn, as1s + N_SVC_, ad1n, hs1s + S1S, b1 + 1 * OUTD,
              row_nn, csr_nn, as1n + N_NODE_, ad1n + N_NODE_, hs1n + S1N, b1 + 3 * OUTD,
              pool + OUTD, N_NODE_};
        int b0n = (N_SVC_ + 7) / 8;
        k_agg1<<<b0n + (N_NODE_ + 7) / 8, 256>>>(a0, a1, b0n);
    }
    k_out<<<1, 64>>>((float*)d_out);
    // s2/evFork/evJoin intentionally not destroyed (illegal mid-capture; bounded leak)
}

// round 17
// speedup vs baseline: 1.8040x; 1.0005x over previous
#include <cuda_runtime.h>
#include <cuda_fp16.h>
#include <math.h>

#define N_SVC_ 100000
#define N_NODE_ 50000
#define FIN 16
#define HD0 128   // HEADS*HID
#define NH 4
#define OUTD 32
#define E_SS_ 800000
#define E_SN_ 400000
#define E_NS_ 400000
#define E_NN_ 400000

// ---------------- static device scratch ----------------
__device__ int g_row_ss[N_SVC_ + 1], g_row_ns[N_SVC_ + 1];
__device__ int g_row_sn[N_NODE_ + 1], g_row_nn[N_NODE_ + 1];
__device__ int g_cur_ss[N_SVC_], g_cur_ns[N_SVC_];
__device__ int g_cur_sn[N_NODE_], g_cur_nn[N_NODE_];
__device__ int g_csr_ss[E_SS_], g_csr_sn[E_SN_], g_csr_ns[E_NS_], g_csr_nn[E_NN_];
__device__ int g_bsumA[4][256];

// layer-0: logits + aggregated-x (64 floats per dst per relation)
__device__ __align__(16) float g_as0s[2][N_SVC_ * NH];   // [0]=ss, [1]=sn (src=svc)
__device__ __align__(16) float g_as0n[2][N_NODE_ * NH];  // [0]=ns, [1]=nn (src=node)
__device__ __align__(16) float g_ad0s[2][N_SVC_ * NH];   // [0]=ss, [1]=ns (dst=svc)
__device__ __align__(16) float g_ad0n[2][N_NODE_ * NH];  // [0]=sn, [1]=nn (dst=node)
__device__ __align__(16) float g_aggx_ss[N_SVC_ * 64];
__device__ __align__(16) float g_aggx_ns[N_SVC_ * 64];
__device__ __align__(16) float g_aggx_sn[N_NODE_ * 64];
__device__ __align__(16) float g_aggx_nn[N_NODE_ * 64];
__device__ __align__(16) float g_hS[N_SVC_ * HD0];
__device__ __align__(16) float g_hN[N_NODE_ * HD0];
// layer-1 features (fp16 gather)
__device__ __align__(16) __half g_hs1s[2][N_SVC_ * OUTD];
__device__ __align__(16) __half g_hs1n[2][N_NODE_ * OUTD];
__device__ float g_as1s[2][N_SVC_];
__device__ float g_as1n[2][N_NODE_];
__device__ float g_ad1s[2][N_SVC_];
__device__ float g_ad1n[2][N_NODE_];
__device__ __align__(16) float g_wdv0[4][FIN * NH];
__device__ __align__(16) float g_wsv0[4][FIN * NH];
__device__ __align__(16) float g_wdv1[4][HD0];
__device__ double g_pool[2 * OUTD];

struct RelDesc {
    const int* src; const int* dst;
    int E, Nd;
    int* row; int* cur; int* csr; int* bsum;
};
struct Rel4 { RelDesc r[4]; };

// ---------------- wdv/wsv precompute + pool zero ----------------
__global__ void k_wdv_all(const float* __restrict__ Ws0, const float* __restrict__ as0,
                          const float* __restrict__ Wd0, const float* __restrict__ ad0,
                          const float* __restrict__ Wd1, const float* __restrict__ ad1) {
    int t = threadIdx.x;  // 256
    {
        int r = t >> 6, f = (t >> 2) & 15, h = t & 3;
        float s1 = 0.f, s2 = 0.f;
        for (int c = 0; c < 32; c++) {
            s1 += Wd0[r * FIN * HD0 + f * HD0 + h * 32 + c] * ad0[r * HD0 + h * 32 + c];
            s2 += Ws0[r * FIN * HD0 + f * HD0 + h * 32 + c] * as0[r * HD0 + h * 32 + c];
        }
        g_wdv0[r][f * NH + h] = s1;
        g_wsv0[r][f * NH + h] = s2;
    }
    for (int i = t; i < 4 * HD0; i += 256) {
        int r = i >> 7, f = i & 127;
        float s = 0.f;
        for (int c = 0; c < OUTD; c++)
            s += Wd1[r * HD0 * OUTD + f * OUTD + c] * ad1[r * OUTD + c];
        g_wdv1[r][f] = s;
    }
    if (t < 2 * OUTD) g_pool[t] = 0.0;
}

// ---------------- CSR build (unchanged) ----------------
__global__ void k_zero_deg(Rel4 R) {
    const RelDesc rd = R.r[blockIdx.y];
    int i = blockIdx.x * 256 + threadIdx.x;
    if (i < rd.Nd) rd.cur[i] = 0;
}
__global__ void k_hist(Rel4 R) {
    const RelDesc rd = R.r[blockIdx.y];
    int e = blockIdx.x * 256 + threadIdx.x;
    if (e < rd.E) atomicAdd(&rd.cur[rd.dst[e]], 1);
}
__global__ void k_bsum(Rel4 R) {
    const RelDesc rd = R.r[blockIdx.y];
    if ((int)blockIdx.x * 512 >= rd.Nd) return;
    __shared__ int sh[512];
    int t = threadIdx.x, i = blockIdx.x * 512 + t;
    sh[t] = (i < rd.Nd) ? rd.cur[i] : 0;
    __syncthreads();
    for (int o = 256; o > 0; o >>= 1) {
        if (t < o) sh[t] += sh[t + o];
        __syncthreads();
    }
    if (t == 0) rd.bsum[blockIdx.x] = sh[0];
}
__global__ void k_bscan(Rel4 R) {
    const RelDesc rd = R.r[blockIdx.x];
    int nb = (rd.Nd + 511) >> 9;
    __shared__ int sh[256];
    int t = threadIdx.x;
    int v = (t < nb) ? rd.bsum[t] : 0;
    sh[t] = v;
    __syncthreads();
    for (int o = 1; o < 256; o <<= 1) {
        int a = (t >= o) ? sh[t - o] : 0;
        __syncthreads();
        sh[t] += a;
        __syncthreads();
    }
    if (t < nb) rd.bsum[t] = sh[t] - v;
    if (t == 255) rd.row[rd.Nd] = sh[255];
}
__global__ void k_rowptr(Rel4 R) {
    const RelDesc rd = R.r[blockIdx.y];
    if ((int)blockIdx.x * 512 >= rd.Nd) return;
    __shared__ int sh[512];
    int t = threadIdx.x, i = blockIdx.x * 512 + t;
    int v = (i < rd.Nd) ? rd.cur[i] : 0;
    sh[t] = v;
    __syncthreads();
    for (int o = 1; o < 512; o <<= 1) {
        int a = (t >= o) ? sh[t - o] : 0;
        __syncthreads();
        sh[t] += a;
        __syncthreads();
    }
    if (i < rd.Nd) {
        int rp = rd.bsum[blockIdx.x] + sh[t] - v;
        rd.row[i] = rp;
        rd.cur[i] = rp;
    }
}
__global__ void k_scatter(Rel4 R) {
    const RelDesc rd = R.r[blockIdx.y];
    int e = blockIdx.x * 256 + threadIdx.x;
    if (e < rd.E) {
        int pos = atomicAdd(&rd.cur[rd.dst[e]], 1);
        rd.csr[pos] = rd.src[e];
    }
}

// ---------------- layer-0 logits ----------------
struct Logit0Job {
    const float* x; int N;
    const float* wsvA; const float* wsvB; const float* wdvA; const float* wdvB;
    float* asA; float* asB; float* adA; float* adB;
};
__global__ void k_logit0(Logit0Job j0, Logit0Job j1, int blocks0) {
    Logit0Job jb = (blockIdx.x < (unsigned)blocks0) ? j0 : j1;
    int bx = (blockIdx.x < (unsigned)blocks0) ? blockIdx.x : blockIdx.x - blocks0;
    int n = bx * 256 + threadIdx.x;
    if (n >= jb.N) return;
    float xv[16];
    float4 t0 = ((const float4*)jb.x)[n * 4 + 0];
    float4 t1 = ((const float4*)jb.x)[n * 4 + 1];
    float4 t2 = ((const float4*)jb.x)[n * 4 + 2];
    float4 t3 = ((const float4*)jb.x)[n * 4 + 3];
    xv[0]=t0.x; xv[1]=t0.y; xv[2]=t0.z; xv[3]=t0.w;
    xv[4]=t1.x; xv[5]=t1.y; xv[6]=t1.z; xv[7]=t1.w;
    xv[8]=t2.x; xv[9]=t2.y; xv[10]=t2.z; xv[11]=t2.w;
    xv[12]=t3.x; xv[13]=t3.y; xv[14]=t3.z; xv[15]=t3.w;
#define DOT4(W, OUT) { \
        float d0=0,d1=0,d2=0,d3=0; \
        _Pragma("unroll") \
        for (int f = 0; f < 16; f++) { \
            float v = xv[f]; \
            d0 += v * (W)[f*4+0]; d1 += v * (W)[f*4+1]; \
            d2 += v * (W)[f*4+2]; d3 += v * (W)[f*4+3]; \
        } \
        ((float4*)(OUT))[n] = make_float4(d0,d1,d2,d3); }
    DOT4(jb.wsvA, jb.asA)
    DOT4(jb.wsvB, jb.asB)
    DOT4(jb.wdvA, jb.adA)
    DOT4(jb.wdvB, jb.adB)
#undef DOT4
}

// ---------------- layer-0 aggregation over raw x (linear-commute), warp/dst ----------------
struct Agg0Job {
    const int* rowA; const int* csrA; const float* asA; const float* adA; const float* xA;
    const int* rowB; const int* csrB; const float* asB; const float* adB; const float* xB;
    float* aggxA; float* aggxB; int Nd;
};
__device__ __forceinline__ float ew_fast(float e) {
    e = fmaxf(e, 0.2f * e);           // leaky_relu(e, 0.2)
    return __expf(e);
}
__device__ __forceinline__ float2 agg0x_rel(const int* __restrict__ row, const int* __restrict__ csr,
                                            const float* __restrict__ asr, const float* __restrict__ adt,
                                            const float* __restrict__ x, int d, int q, int h) {
    float adv = adt[d * NH + h];
    int i0 = row[d], i1 = row[d + 1];
    float ax = 0.f, ay = 0.f, den = 0.f;
    const float2* x2 = (const float2*)x;
    int i = i0;
    for (; i + 2 <= i1; i += 2) {
        int s0 = csr[i], s1 = csr[i + 1];
        float w0 = ew_fast(asr[s0 * NH + h] + adv);
        float w1 = ew_fast(asr[s1 * NH + h] + adv);
        float2 v0 = x2[s0 * 8 + q];
        float2 v1 = x2[s1 * 8 + q];
        den += w0 + w1;
        ax += w0 * v0.x + w1 * v1.x;
        ay += w0 * v0.y + w1 * v1.y;
    }
    if (i < i1) {
        int s = csr[i];
        float w = ew_fast(asr[s * NH + h] + adv);
        float2 v = x2[s * 8 + q];
        den += w;
        ax += w * v.x;
        ay += w * v.y;
    }
    float inv = 1.f / (den + 1e-16f);
    return make_float2(ax * inv, ay * inv);
}
__global__ void k_agg0(Agg0Job j0, Agg0Job j1, int blocks0) {
    Agg0Job jb = (blockIdx.x < (unsigned)blocks0) ? j0 : j1;
    int bx = (blockIdx.x < (unsigned)blocks0) ? blockIdx.x : blockIdx.x - blocks0;
    int d = bx * 8 + (threadIdx.x >> 5);
    if (d >= jb.Nd) return;
    int lane = threadIdx.x & 31, h = lane >> 3, q = lane & 7;
    float2 rA = agg0x_rel(jb.rowA, jb.csrA, jb.asA, jb.adA, jb.xA, d, q, h);
    float2 rB = agg0x_rel(jb.rowB, jb.csrB, jb.asB, jb.adB, jb.xB, d, q, h);
    ((float2*)jb.aggxA)[(size_t)d * 32 + lane] = rA;   // [h*16 + q*2] floats
    ((float2*)jb.aggxB)[(size_t)d * 32 + lane] = rB;
}

// ---------------- layer-0 post: out = 0.5*(aggxA@WsA + aggxB@WsB + bA + bB), ELU ----------------
struct Post0Job {
    const float* aggxA; const float* aggxB;
    const float* WsA; const float* WsB;
    const float* bA; const float* bB;
    float* hout; int N;
};
__global__ void k_post0(Post0Job j0, Post0Job j1, int blocks0) {
    Post0Job jb = (blockIdx.x < (unsigned)blocks0) ? j0 : j1;
    int bx = (blockIdx.x < (unsigned)blocks0) ? blockIdx.x : blockIdx.x - blocks0;
    __shared__ float sWa[FIN * HD0], sWb[FIN * HD0];
    __shared__ float sxa[32 * 64], sxb[32 * 64];
    int t = threadIdx.x;  // 128
    for (int i = t; i < FIN * HD0; i += 128) { sWa[i] = jb.WsA[i]; sWb[i] = jb.WsB[i]; }
    int n0 = bx * 32;
    int lim = jb.N - n0; if (lim > 32) lim = 32;
    for (int i = t; i < lim * 64; i += 128) {
        sxa[i] = jb.aggxA[(size_t)n0 * 64 + i];
        sxb[i] = jb.aggxB[(size_t)n0 * 64 + i];
    }
    __syncthreads();
    int h = t >> 5;
    float ba = jb.bA[t], bb = jb.bB[t];
    for (int jj = 0; jj < lim; jj++) {
        const float* axA = sxa + jj * 64 + h * 16;
        const float* axB = sxb + jj * 64 + h * 16;
        float sA = 0.f, sB = 0.f;
#pragma unroll
        for (int f = 0; f < 16; f++) {
            sA += axA[f] * sWa[f * HD0 + t];
            sB += axB[f] * sWb[f * HD0 + t];
        }
        float o = 0.5f * (sA + sB + ba + bb);
        jb.hout[(size_t)(n0 + jj) * HD0 + t] = o > 0.f ? o : expm1f(o);
    }
}

// ---------------- layer-1 fused dense (fp16 stores) ----------------
struct Feat1Job {
    const float* h; int N;
    const float* Wa; const float* Wb; const float* atta; const float* attb;
    const float* wdvA; const float* wdvB;
    __half* h1a; __half* h1b; float* asa; float* asb; float* adA; float* adB;
};
__global__ void k_feat1(Feat1Job j0, Feat1Job j1, int blocks0) {
    Feat1Job jb = (blockIdx.x < (unsigned)blocks0) ? j0 : j1;
    int bx = (blockIdx.x < (unsigned)blocks0) ? blockIdx.x : blockIdx.x - blocks0;
    __shared__ float sWa[HD0 * OUTD], sWb[HD0 * OUTD];
    __shared__ float sa[OUTD], sb[OUTD], swA[HD0], swB[HD0];
    int tid = threadIdx.x;  // 256
    for (int i = tid; i < HD0 * OUTD; i += 256) { sWa[i] = jb.Wa[i]; sWb[i] = jb.Wb[i]; }
    if (tid < OUTD) { sa[tid] = jb.atta[tid]; sb[tid] = jb.attb[tid]; }
    if (tid >= 64 && tid < 64 + HD0) { swA[tid - 64] = jb.wdvA[tid - 64]; swB[tid - 64] = jb.wdvB[tid - 64]; }
    __syncthreads();
    int warp = tid >> 5, lane = tid & 31;
    for (int t = 0; t < 4; t++) {
        int n = bx * 32 + warp * 4 + t;
        if (n >= jb.N) break;
        float4 hv = ((const float4*)jb.h)[(size_t)n * 32 + lane];
        float va = 0.f, vb = 0.f;
#pragma unroll
        for (int f = 0; f < HD0; f++) {
            float hf = __shfl_sync(~0u, ((const float*)&hv)[f & 3], f >> 2);
            va += hf * sWa[f * OUTD + lane];
            vb += hf * sWb[f * OUTD + lane];
        }
        float va_n = __shfl_down_sync(~0u, va, 1);
        float vb_n = __shfl_down_sync(~0u, vb, 1);
        if (!(lane & 1)) {
            ((__half2*)jb.h1a)[(size_t)n * 16 + (lane >> 1)] = __floats2half2_rn(va, va_n);
            ((__half2*)jb.h1b)[(size_t)n * 16 + (lane >> 1)] = __floats2half2_rn(vb, vb_n);
        }
        float pa = va * sa[lane], pb = vb * sb[lane];
        float4 wA = ((const float4*)swA)[lane], wB = ((const float4*)swB)[lane];
        float da = hv.x * wA.x + hv.y * wA.y + hv.z * wA.z + hv.w * wA.w;
        float db = hv.x * wB.x + hv.y * wB.y + hv.z * wB.z + hv.w * wB.w;
#pragma unroll
        for (int o = 16; o > 0; o >>= 1) {
            pa += __shfl_xor_sync(~0u, pa, o);
            pb += __shfl_xor_sync(~0u, pb, o);
            da += __shfl_xor_sync(~0u, da, o);
            db += __shfl_xor_sync(~0u, db, o);
        }
        if (lane == 0) { jb.asa[n] = pa; jb.asb[n] = pb; jb.adA[n] = da; jb.adB[n] = db; }
    }
}

// ---------------- layer-1 aggregation (fp16 gather) + fused mean-pool ----------------
struct Agg1Job {
    const int* rowA; const int* csrA; const float* asA; const float* adA;
    const __half* h1A; const float* bA;
    const int* rowB; const int* csrB; const float* asB; const float* adB;
    const __half* h1B; const float* bB;
    double* pool; int Nd;
};
__device__ __forceinline__ float agg1_rel(const int* __restrict__ row, const int* __restrict__ csr,
                                          const float* __restrict__ asr, const float* __restrict__ adt,
                                          const __half* __restrict__ h1, int d, int lane) {
    float adv = adt[d];
    int i0 = row[d], i1 = row[d + 1];
    float acc = 0.f, den = 0.f;
    int i = i0;
    for (; i + 2 <= i1; i += 2) {
        int s0 = csr[i], s1 = csr[i + 1];
        float w0 = ew_fast(asr[s0] + adv);
        float w1 = ew_fast(asr[s1] + adv);
        float v0 = __half2float(h1[(size_t)s0 * OUTD + lane]);
        float v1 = __half2float(h1[(size_t)s1 * OUTD + lane]);
        den += w0 + w1;
        acc += w0 * v0 + w1 * v1;
    }
    if (i < i1) {
        int s = csr[i];
        float w = ew_fast(asr[s] + adv);
        den += w;
        acc += w * __half2float(h1[(size_t)s * OUTD + lane]);
    }
    return acc / (den + 1e-16f);
}
__global__ void k_agg1(Agg1Job j0, Agg1Job j1, int blocks0) {
    Agg1Job jb = (blockIdx.x < (unsigned)blocks0) ? j0 : j1;
    int bx = (blockIdx.x < (unsigned)blocks0) ? blockIdx.x : blockIdx.x - blocks0;
    __shared__ double sp[8][33];
    int warp = threadIdx.x >> 5, lane = threadIdx.x & 31;
    int d = bx * 8 + warp;
    float res = 0.f;
    if (d < jb.Nd) {
        float rA = agg1_rel(jb.rowA, jb.csrA, jb.asA, jb.adA, jb.h1A, d, lane);
        float rB = agg1_rel(jb.rowB, jb.csrB, jb.asB, jb.adB, jb.h1B, d, lane);
        res = 0.5f * (rA + rB + jb.bA[lane] + jb.bB[lane]);
    }
    sp[warp][lane] = (double)res;
    __syncthreads();
    if (warp == 0) {
        double t = sp[0][lane];
#pragma unroll
        for (int k = 1; k < 8; k++) t += sp[k][lane];
        asm volatile("red.global.add.f64 [%0], %1;" :: "l"(&jb.pool[lane]), "d"(t) : "memory");
    }
}

__global__ void k_out(float* __restrict__ out) {
    int t = threadIdx.x;  // 64
    double cnt = (t < OUTD) ? (double)N_SVC_ : (double)N_NODE_;
    out[t] = (float)(g_pool[t] / cnt);
}

// ---------------- host driver (fork/join) ----------------
extern "C" void kernel_launch(void* const* d_in, const int* in_sizes, int n_in,
                              void* d_out, int out_size) {
    const float* x_svc = (const float*)d_in[0];
    const float* x_node = (const float*)d_in[1];
    const int* ss_s = (const int*)d_in[2]; const int* ss_d = (const int*)d_in[3];
    const int* sn_s = (const int*)d_in[4]; const int* sn_d = (const int*)d_in[5];
    const int* ns_s = (const int*)d_in[6]; const int* ns_d = (const int*)d_in[7];
    const int* nn_s = (const int*)d_in[8]; const int* nn_d = (const int*)d_in[9];
    const float* Ws0 = (const float*)d_in[10];
    const float* Wd0 = (const float*)d_in[11];
    const float* as0 = (const float*)d_in[12];
    const float* ad0 = (const float*)d_in[13];
    const float* b0  = (const float*)d_in[14];
    const float* Ws1 = (const float*)d_in[15];
    const float* Wd1 = (const float*)d_in[16];
    const float* as1 = (const float*)d_in[17];
    const float* ad1 = (const float*)d_in[18];
    const float* b1  = (const float*)d_in[19];
    int E_ss = in_sizes[2], E_sn = in_sizes[4], E_ns = in_sizes[6], E_nn = in_sizes[8];

    int *row_ss, *row_sn, *row_ns, *row_nn, *cur_ss, *cur_sn, *cur_ns, *cur_nn;
    int *csr_ss, *csr_sn, *csr_ns, *csr_nn, *bsumA;
    float *as0s, *as0n, *ad0s, *ad0n, *hS, *hN;
    float *aggx_ss, *aggx_ns, *aggx_sn, *aggx_nn;
    __half *hs1s, *hs1n;
    float *as1s, *as1n, *ad1s, *ad1n, *wdv0, *wsv0, *wdv1;
    double* pool;
    cudaGetSymbolAddress((void**)&row_ss, g_row_ss);
    cudaGetSymbolAddress((void**)&row_sn, g_row_sn);
    cudaGetSymbolAddress((void**)&row_ns, g_row_ns);
    cudaGetSymbolAddress((void**)&row_nn, g_row_nn);
    cudaGetSymbolAddress((void**)&cur_ss, g_cur_ss);
    cudaGetSymbolAddress((void**)&cur_sn, g_cur_sn);
    cudaGetSymbolAddress((void**)&cur_ns, g_cur_ns);
    cudaGetSymbolAddress((void**)&cur_nn, g_cur_nn);
    cudaGetSymbolAddress((void**)&csr_ss, g_csr_ss);
    cudaGetSymbolAddress((void**)&csr_sn, g_csr_sn);
    cudaGetSymbolAddress((void**)&csr_ns, g_csr_ns);
    cudaGetSymbolAddress((void**)&csr_nn, g_csr_nn);
    cudaGetSymbolAddress((void**)&bsumA, g_bsumA);
    cudaGetSymbolAddress((void**)&as0s, g_as0s);
    cudaGetSymbolAddress((void**)&as0n, g_as0n);
    cudaGetSymbolAddress((void**)&ad0s, g_ad0s);
    cudaGetSymbolAddress((void**)&ad0n, g_ad0n);
    cudaGetSymbolAddress((void**)&aggx_ss, g_aggx_ss);
    cudaGetSymbolAddress((void**)&aggx_ns, g_aggx_ns);
    cudaGetSymbolAddress((void**)&aggx_sn, g_aggx_sn);
    cudaGetSymbolAddress((void**)&aggx_nn, g_aggx_nn);
    cudaGetSymbolAddress((void**)&hS, g_hS);
    cudaGetSymbolAddress((void**)&hN, g_hN);
    cudaGetSymbolAddress((void**)&hs1s, g_hs1s);
    cudaGetSymbolAddress((void**)&hs1n, g_hs1n);
    cudaGetSymbolAddress((void**)&as1s, g_as1s);
    cudaGetSymbolAddress((void**)&as1n, g_as1n);
    cudaGetSymbolAddress((void**)&ad1s, g_ad1s);
    cudaGetSymbolAddress((void**)&ad1n, g_ad1n);
    cudaGetSymbolAddress((void**)&wdv0, g_wdv0);
    cudaGetSymbolAddress((void**)&wsv0, g_wsv0);
    cudaGetSymbolAddress((void**)&wdv1, g_wdv1);
    cudaGetSymbolAddress((void**)&pool, g_pool);

    Rel4 R;
    R.r[0] = {ss_s, ss_d, E_ss, N_SVC_,  row_ss, cur_ss, csr_ss, bsumA + 0 * 256};
    R.r[1] = {sn_s, sn_d, E_sn, N_NODE_, row_sn, cur_sn, csr_sn, bsumA + 1 * 256};
    R.r[2] = {ns_s, ns_d, E_ns, N_SVC_,  row_ns, cur_ns, csr_ns, bsumA + 2 * 256};
    R.r[3] = {nn_s, nn_d, E_nn, N_NODE_, row_nn, cur_nn, csr_nn, bsumA + 3 * 256};

    int maxE = E_ss > E_sn ? E_ss : E_sn;
    if (E_ns > maxE) maxE = E_ns;
    if (E_nn > maxE) maxE = E_nn;

    // fork: CSR build on side stream, dense chain on main (legacy) stream
    cudaStream_t s2;
    cudaEvent_t evFork, evJoin;
    cudaStreamCreateWithFlags(&s2, cudaStreamNonBlocking);
    cudaEventCreateWithFlags(&evFork, cudaEventDisableTiming);
    cudaEventCreateWithFlags(&evJoin, cudaEventDisableTiming);

    cudaEventRecord(evFork, 0);
    cudaStreamWaitEvent(s2, evFork, 0);

    // --- side stream: CSR build ---
    k_zero_deg<<<dim3((N_SVC_ + 255) / 256, 4), 256, 0, s2>>>(R);
    k_hist<<<dim3((maxE + 255) / 256, 4), 256, 0, s2>>>(R);
    k_bsum<<<dim3((N_SVC_ + 511) / 512, 4), 512, 0, s2>>>(R);
    k_bscan<<<4, 256, 0, s2>>>(R);
    k_rowptr<<<dim3((N_SVC_ + 511) / 512, 4), 512, 0, s2>>>(R);
    k_scatter<<<dim3((maxE + 255) / 256, 4), 256, 0, s2>>>(R);
    cudaEventRecord(evJoin, s2);

    // --- main stream: layer-0 logits ---
    k_wdv_all<<<1, 256>>>(Ws0, as0, Wd0, ad0, Wd1, ad1);
    {
        Logit0Job f0, f1;
        f0 = {x_svc, N_SVC_, wsv0 + 0 * 64, wsv0 + 1 * 64, wdv0 + 0 * 64, wdv0 + 2 * 64,
              as0s, as0s + N_SVC_ * NH, ad0s, ad0s + N_SVC_ * NH};
        f1 = {x_node, N_NODE_, wsv0 + 2 * 64, wsv0 + 3 * 64, wdv0 + 1 * 64, wdv0 + 3 * 64,
              as0n, as0n + N_NODE_ * NH, ad0n, ad0n + N_NODE_ * NH};
        int b0n = (N_SVC_ + 255) / 256;
        k_logit0<<<b0n + (N_NODE_ + 255) / 256, 256>>>(f0, f1, b0n);
    }

    // join: agg0 needs CSR + logits
    cudaStreamWaitEvent(0, evJoin, 0);
    {
        Agg0Job a0, a1;
        a0 = {row_ss, csr_ss, as0s, ad0s, x_svc,
              row_ns, csr_ns, as0n, ad0s + N_SVC_ * NH, x_node,
              aggx_ss, aggx_ns, N_SVC_};
        a1 = {row_sn, csr_sn, as0s + N_SVC_ * NH, ad0n, x_svc,
              row_nn, csr_nn, as0n + N_NODE_ * NH, ad0n + N_NODE_ * NH, x_node,
              aggx_sn, aggx_nn, N_NODE_};
        int b0n = (N_SVC_ + 7) / 8;
        k_agg0<<<b0n + (N_NODE_ + 7) / 8, 256>>>(a0, a1, b0n);
    }
    {
        Post0Job p0, p1;
        p0 = {aggx_ss, aggx_ns, Ws0 + 0 * FIN * HD0, Ws0 + 2 * FIN * HD0,
              b0 + 0 * HD0, b0 + 2 * HD0, hS, N_SVC_};
        p1 = {aggx_sn, aggx_nn, Ws0 + 1 * FIN * HD0, Ws0 + 3 * FIN * HD0,
              b0 + 1 * HD0, b0 + 3 * HD0, hN, N_NODE_};
        int b0n = (N_SVC_ + 31) / 32;
        k_post0<<<b0n + (N_NODE_ + 31) / 32, 128>>>(p0, p1, b0n);
    }

    // ---- layer 1 ----
    size_t S1S = (size_t)N_SVC_ * OUTD, S1N = (size_t)N_NODE_ * OUTD;
    {
        Feat1Job f0, f1;
        f0 = {hS, N_SVC_, Ws1 + 0 * HD0 * OUTD, Ws1 + 1 * HD0 * OUTD,
              as1 + 0 * OUTD, as1 + 1 * OUTD, wdv1 + 0 * HD0, wdv1 + 2 * HD0,
              hs1s, hs1s + S1S, as1s, as1s + N_SVC_, ad1s, ad1s + N_SVC_};
        f1 = {hN, N_NODE_, Ws1 + 2 * HD0 * OUTD, Ws1 + 3 * HD0 * OUTD,
              as1 + 2 * OUTD, as1 + 3 * OUTD, wdv1 + 1 * HD0, wdv1 + 3 * HD0,
              hs1n, hs1n + S1N, as1n, as1n + N_NODE_, ad1n, ad1n + N_NODE_};
        int b0n = (N_SVC_ + 31) / 32;
        k_feat1<<<b0n + (N_NODE_ + 31) / 32, 256>>>(f0, f1, b0n);
    }
    {
        Agg1Job a0, a1;
        a0 = {row_ss, csr_ss, as1s, ad1s, hs1s, b1 + 0 * OUTD,
              row_ns, csr_ns, as1n, ad1s + N_SVC_, hs1n, b1 + 2 * OUTD,
              pool, N_SVC_};
        a1 = {row_sn, csr_sn, as1s + N_SVC_, ad1n, hs1s + S1S, b1 + 1 * OUTD,
              row_nn, csr_nn, as1n + N_NODE_, ad1n + N_NODE_, hs1n + S1N, b1 + 3 * OUTD,
              pool + OUTD, N_NODE_};
        int b0n = (N_SVC_ + 7) / 8;
        k_agg1<<<b0n + (N_NODE_ + 7) / 8, 256>>>(a0, a1, b0n);
    }
    k_out<<<1, 64>>>((float*)d_out);
    // s2/evFork/evJoin intentionally not destroyed (illegal mid-capture; bounded leak)
}